// round 1
// baseline (speedup 1.0000x reference)
#include <cuda_runtime.h>

// ---------------- problem constants ----------------
#define B_      2
#define NPIX    576          // 24*24
#define NL      171
#define NBL     (B_*NL)      // 342
#define ICH     768
#define OC1     512
#define OC2     512
#define M1      (OC1*9)      // 4608
#define N1      (B_*NPIX)    // 1152
#define K2      (OC1*9)      // 4608
#define IMG_ELEMS  (577*B_*768)          // 886272
#define TXT_ELEMS  (B_*77*NL*512)        // 13483008

// ---------------- scratch (static device globals; no allocation) ----------------
__device__ float g_Xp[ICH * N1];      // x packed [ic][n=b*576+pix]
__device__ float g_W1r[ICH * M1];     // w1 transposed [ic][oc1*9+ab]
__device__ float g_P1 [N1 * M1];      // GEMM1 out [n][oc1*9+ab]
__device__ float g_W2r[K2 * OC2];     // w2 transposed [oc1*9+k][oc2]
__device__ float g_Tb [K2 * NBL];     // T (+bias terms) [oc1*9+k][bl]
__device__ float g_out512[NBL * OC2]; // [bl][oc2]
__device__ int   g_m[N1];             // labels per (b,pix)

// ---------------- prep kernels ----------------
__global__ void pack_x_k(const float* __restrict__ noise) {
    int i = blockIdx.x * blockDim.x + threadIdx.x;
    if (i >= ICH * N1) return;
    int k = i / N1;
    int r = i % N1;
    int b = r / NPIX, pix = r % NPIX;
    // x[b,ic,pix] = noise[b, ic, 1+pix]  (drop CLS token)
    g_Xp[i] = noise[b * ICH * 577 + k * 577 + 1 + pix];
}

__global__ void labels_k(const int* __restrict__ targets) {
    int i = blockIdx.x * blockDim.x + threadIdx.x;
    if (i >= N1) return;
    int b = i / NPIX, pix = i % NPIX;
    int pi = pix / 24, qj = pix % 24;
    // nearest-neighbor: ih = (i*384)//24 = 16*i
    g_m[i] = targets[b * 147456 + (pi * 16) * 384 + qj * 16];
}

__global__ void w1t_k(const float* __restrict__ w1) {
    int i = blockIdx.x * blockDim.x + threadIdx.x;
    if (i >= ICH * M1) return;
    int ic = i / M1;
    int rem = i % M1;            // oc1*9 + ab
    g_W1r[i] = w1[(rem / 9) * (ICH * 9) + ic * 9 + (rem % 9)];
}

__global__ void w2t_k(const float* __restrict__ w2) {
    int i = blockIdx.x * blockDim.x + threadIdx.x;
    if (i >= K2 * OC2) return;
    int kp  = i / OC2;           // oc1*9 + k
    int oc2 = i % OC2;
    g_W2r[i] = w2[oc2 * K2 + kp];
}

// ---------------- generic SMEM-tiled GEMM:  C[N][M] = A[K][N]^T * B[K][M] (+bias) ----------------
template<int BM, int BN, int BK, int TM, int TN, int NT>
__global__ __launch_bounds__(NT) void gemm_tn(
    const float* __restrict__ A,    // [K][N]
    const float* __restrict__ Bm,   // [K][M]
    float* __restrict__ C,          // [N][M]
    const float* __restrict__ bias, // [M] or nullptr
    int N, int M, int K)
{
    __shared__ float As[BK][BM];
    __shared__ float Bs[BK][BN];
    const int tid = threadIdx.x;
    const int n0 = blockIdx.x * BM;
    const int m0 = blockIdx.y * BN;

    float acc[TM][TN];
#pragma unroll
    for (int i = 0; i < TM; i++)
#pragma unroll
        for (int j = 0; j < TN; j++) acc[i][j] = 0.f;

    const int tr = (tid / (BN / TN)) * TM;
    const int tc = (tid % (BN / TN)) * TN;

    for (int k0 = 0; k0 < K; k0 += BK) {
#pragma unroll
        for (int it = 0; it < (BK * BM) / NT; it++) {
            int i = tid + it * NT;
            int r = i / BM, c = i % BM;
            int n = n0 + c;
            As[r][c] = (n < N) ? A[(k0 + r) * N + n] : 0.f;
        }
#pragma unroll
        for (int it = 0; it < (BK * BN) / NT; it++) {
            int i = tid + it * NT;
            int r = i / BN, c = i % BN;
            Bs[r][c] = Bm[(k0 + r) * M + m0 + c];
        }
        __syncthreads();
#pragma unroll
        for (int kk = 0; kk < BK; kk++) {
            float ra[TM], rb[TN];
#pragma unroll
            for (int i = 0; i < TM; i++) ra[i] = As[kk][tr + i];
#pragma unroll
            for (int j = 0; j < TN; j++) rb[j] = Bs[kk][tc + j];
#pragma unroll
            for (int i = 0; i < TM; i++)
#pragma unroll
                for (int j = 0; j < TN; j++) acc[i][j] += ra[i] * rb[j];
        }
        __syncthreads();
    }

#pragma unroll
    for (int i = 0; i < TM; i++) {
        int n = n0 + tr + i;
        if (n < N) {
#pragma unroll
            for (int j = 0; j < TN; j++) {
                float v = acc[i][j];
                if (bias) v += bias[m0 + tc + j];
                C[n * M + m0 + tc + j] = v;
            }
        }
    }
}

// ---------------- sparse per-label box-sum accumulation ----------------
// Tb[(oc1*9 + dr*3+dc)][bl] = ( T_raw + nr[dr]*nc[dc]*b1[oc1] ) / 576
// T_raw[bl,oc1,dr,dc] = sum over pixels with label l of
//                       sum_{a,b in valid interval} P1[b,oc1,a,b,pix]
__global__ __launch_bounds__(512) void acc_kernel(const float* __restrict__ b1) {
    const int bl = blockIdx.x;
    const int b = bl / NL;
    const int l = bl % NL;
    const int oc1 = threadIdx.x;

    __shared__ int msh[NPIX];
    for (int i = threadIdx.x; i < NPIX; i += 512) msh[i] = g_m[b * NPIX + i];
    __syncthreads();

    // row/col interval [lo,hi] that pixel index must lie in for kernel tap a
    // (dr in {0,1,2}: pooled-row ranges [0,4],[0,5],[1,5] -> y1 rows [0,19],[0,23],[4,23])
    const int lo[3][3] = {{0, 0, 1}, {0, 0, 1}, {3, 4, 5}};
    const int hi[3][3] = {{18, 19, 20}, {22, 23, 23}, {22, 23, 23}};

    float T9[9];
#pragma unroll
    for (int k = 0; k < 9; k++) T9[k] = 0.f;

    for (int pix = 0; pix < NPIX; pix++) {
        if (msh[pix] != l) continue;
        const float* v = &g_P1[(b * NPIX + pix) * M1 + oc1 * 9];
        float vv[9];
#pragma unroll
        for (int t = 0; t < 9; t++) vv[t] = v[t];
        int p = pix / 24, q = pix % 24;

        float rs[3][3];  // [dr][b-col-tap]
#pragma unroll
        for (int dr = 0; dr < 3; dr++)
#pragma unroll
            for (int bb = 0; bb < 3; bb++) {
                float s = 0.f;
#pragma unroll
                for (int a = 0; a < 3; a++)
                    if (p >= lo[dr][a] && p <= hi[dr][a]) s += vv[a * 3 + bb];
                rs[dr][bb] = s;
            }
#pragma unroll
        for (int dr = 0; dr < 3; dr++)
#pragma unroll
            for (int dc = 0; dc < 3; dc++) {
                float s = 0.f;
#pragma unroll
                for (int bb = 0; bb < 3; bb++)
                    if (q >= lo[dc][bb] && q <= hi[dc][bb]) s += rs[dr][bb];
                T9[dr * 3 + dc] += s;
            }
    }

    const float nrc[3] = {20.f, 24.f, 20.f};
    float bb1 = b1[oc1];
#pragma unroll
    for (int k = 0; k < 9; k++) {
        float t = (T9[k] + nrc[k / 3] * nrc[k % 3] * bb1) * (1.0f / 576.0f);
        g_Tb[(oc1 * 9 + k) * NBL + bl] = t;
    }
}

// ---------------- outputs ----------------
__global__ void image_k(const float* __restrict__ noise, float* __restrict__ out) {
    int i = blockIdx.x * blockDim.x + threadIdx.x;
    if (i >= IMG_ELEMS) return;
    int c = i % 768;
    int b = (i / 768) % B_;
    int s = i / (768 * B_);
    out[i] = noise[b * 443136 + c * 577 + s];
}

__global__ void expand_k(const float* __restrict__ w3, const float* __restrict__ b3,
                         float* __restrict__ out) {
    int i = blockIdx.x * blockDim.x + threadIdx.x;
    if (i >= TXT_ELEMS) return;
    int c = i & 511;
    int l = (i >> 9) % NL;
    int o = (i / (512 * NL)) % 77;
    int b = i / (512 * NL * 77);
    out[i] = w3[o] * g_out512[(b * NL + l) * OC2 + c] + b3[o];
}

// ---------------- launch ----------------
extern "C" void kernel_launch(void* const* d_in, const int* in_sizes, int n_in,
                              void* d_out, int out_size) {
    const float* noise   = (const float*)d_in[0];
    const int*   targets = (const int*)  d_in[1];
    const float* w1      = (const float*)d_in[2];
    const float* b1      = (const float*)d_in[3];
    const float* w2      = (const float*)d_in[4];
    const float* b2      = (const float*)d_in[5];
    const float* w3      = (const float*)d_in[6];
    const float* b3      = (const float*)d_in[7];
    float* out      = (float*)d_out;
    float* out_img  = out;              // 886272 elems
    float* out_text = out + IMG_ELEMS;  // 13483008 elems

    float *pXp, *pW1r, *pP1, *pW2r, *pTb, *pOut512;
    cudaGetSymbolAddress((void**)&pXp,     g_Xp);
    cudaGetSymbolAddress((void**)&pW1r,    g_W1r);
    cudaGetSymbolAddress((void**)&pP1,     g_P1);
    cudaGetSymbolAddress((void**)&pW2r,    g_W2r);
    cudaGetSymbolAddress((void**)&pTb,     g_Tb);
    cudaGetSymbolAddress((void**)&pOut512, g_out512);

    pack_x_k<<<864, 1024>>>(noise);                       // 884736 elems
    labels_k<<<2, 576>>>(targets);
    w1t_k<<<3456, 1024>>>(w1);                            // 3538944
    w2t_k<<<2304, 1024>>>(w2);                            // 2359296

    // GEMM1: P1[1152][4608] = Xp[768][1152]^T * W1r[768][4608]
    gemm_tn<128, 128, 16, 8, 8, 256>
        <<<dim3(N1 / 128, M1 / 128), 256>>>(pXp, pW1r, pP1, nullptr, N1, M1, ICH);

    // per-label sparse accumulation -> Tb[4608][342]
    acc_kernel<<<NBL, 512>>>(b1);

    // GEMM2: out512[342][512] = Tb[4608][342]^T * W2r[4608][512] + b2
    gemm_tn<64, 32, 16, 2, 4, 256>
        <<<dim3((NBL + 63) / 64, OC2 / 32), 256>>>(pTb, pW2r, pOut512, b2, NBL, OC2, K2);

    image_k<<<866, 1024>>>(noise, out_img);
    expand_k<<<13167, 1024>>>(w3, b3, out_text);
}

// round 3
// speedup vs baseline: 3.9869x; 3.9869x over previous
#include <cuda_runtime.h>
#include <cuda_bf16.h>
#include <cstdint>

// ---------------- problem constants ----------------
#define B_      2
#define NPIX    576
#define NL      171
#define NBL     342
#define NPAD    384          // padded N for GEMM2 (3 x 128)
#define ICH     768
#define OC1     512
#define OC2     512
#define M1      4608         // OC1*9
#define N1      1152         // B_*NPIX
#define K1      768
#define K2      4608
#define KSPLIT  6
#define IMG_ELEMS  (577*B_*768)
#define TXT_ELEMS  (B_*77*NL*512)

// ---------------- scratch (device globals; zero-initialized at load) ----------------
__device__ __align__(128) __nv_bfloat16 g_A1b[M1 * K1];   // w1 rearranged [m=oc1*9+ab][ic]
__device__ __align__(128) __nv_bfloat16 g_Bxb[N1 * K1];   // x transposed  [n][ic]
__device__ __align__(128) float         g_P1[(size_t)N1 * M1];
__device__ __align__(128) __nv_bfloat16 g_W2b[OC2 * K2];  // w2 cast (already K-major)
__device__ __align__(128) __nv_bfloat16 g_Tbb[NPAD * K2]; // [bl][k]; rows >=342 stay zero
__device__ __align__(128) float         g_part[KSPLIT * NPAD * OC2];
__device__ __align__(128) float         g_out512[NPAD * OC2];
__device__ int g_m[N1];

// ---------------- PTX helpers (sm_80 base-target features only) ----------------
__device__ __forceinline__ uint32_t smem_u32(const void* p) {
    uint32_t a;
    asm("{ .reg .u64 t; cvta.to.shared.u64 t, %1; cvt.u32.u64 %0, t; }" : "=r"(a) : "l"(p));
    return a;
}
__device__ __forceinline__ void cpasync16(uint32_t dst, const void* src) {
    asm volatile("cp.async.cg.shared.global [%0], [%1], 16;\n" :: "r"(dst), "l"(src));
}
#define CP_COMMIT() asm volatile("cp.async.commit_group;\n" ::: "memory")

__device__ __forceinline__ void ldsm_x4(uint32_t& r0, uint32_t& r1, uint32_t& r2,
                                        uint32_t& r3, uint32_t addr) {
    asm volatile("ldmatrix.sync.aligned.m8n8.x4.shared.b16 {%0,%1,%2,%3}, [%4];"
                 : "=r"(r0), "=r"(r1), "=r"(r2), "=r"(r3) : "r"(addr));
}
__device__ __forceinline__ void mma_bf16(float* c, const uint32_t* a, const uint32_t* b) {
    asm volatile("mma.sync.aligned.m16n8k16.row.col.f32.bf16.bf16.f32 "
                 "{%0,%1,%2,%3}, {%4,%5,%6,%7}, {%8,%9}, {%0,%1,%2,%3};"
                 : "+f"(c[0]), "+f"(c[1]), "+f"(c[2]), "+f"(c[3])
                 : "r"(a[0]), "r"(a[1]), "r"(a[2]), "r"(a[3]), "r"(b[0]), "r"(b[1]));
}

// ---------------- prep kernels ----------------
__global__ void labels_k(const int* __restrict__ targets) {
    int i = blockIdx.x * blockDim.x + threadIdx.x;
    if (i >= N1) return;
    int b = i / NPIX, pix = i % NPIX;
    int pi = pix / 24, qj = pix % 24;
    g_m[i] = targets[b * 147456 + (pi * 16) * 384 + qj * 16];
}

// image_noise = transpose: out[s][b][c] = noise[b][c][s]
__global__ void img_tr_k(const float* __restrict__ noise, float* __restrict__ out) {
    __shared__ float tile[32][33];
    int b = blockIdx.z;
    int s0 = blockIdx.x * 32, c0 = blockIdx.y * 32;
    int tx = threadIdx.x, ty = threadIdx.y;
    for (int r = ty; r < 32; r += 8) {
        int s = s0 + tx;
        if (s < 577) tile[r][tx] = noise[(size_t)b * 443136 + (c0 + r) * 577 + s];
    }
    __syncthreads();
    for (int r = ty; r < 32; r += 8) {
        int s = s0 + r;
        if (s < 577) out[(size_t)s * (B_ * 768) + b * 768 + c0 + tx] = tile[tx][r];
    }
}

// g_Bxb[(b*576+pix)][ic] = bf16(noise[b][ic][1+pix])
__global__ void xpack_k(const float* __restrict__ noise) {
    __shared__ float tile[32][33];
    int b = blockIdx.z;
    int p0 = blockIdx.x * 32, c0 = blockIdx.y * 32;
    int tx = threadIdx.x, ty = threadIdx.y;
    for (int r = ty; r < 32; r += 8)
        tile[r][tx] = noise[(size_t)b * 443136 + (c0 + r) * 577 + 1 + p0 + tx];
    __syncthreads();
    for (int r = ty; r < 32; r += 8)
        g_Bxb[(size_t)(b * NPIX + p0 + r) * ICH + c0 + tx] = __float2bfloat16(tile[tx][r]);
}

// g_A1b[(oc1*9+ab)][ic] = bf16(w1[oc1][ic][ab])
__global__ __launch_bounds__(256) void w1r_k(const float* __restrict__ w1) {
    __shared__ float sm[ICH * 9];
    int oc1 = blockIdx.x;
    const float* src = w1 + (size_t)oc1 * ICH * 9;
    for (int i = threadIdx.x; i < ICH * 9; i += 256) sm[i] = src[i];
    __syncthreads();
    __nv_bfloat16* dst = g_A1b + (size_t)oc1 * 9 * K1;
    for (int i = threadIdx.x; i < ICH * 9; i += 256) {
        int ab = i / ICH, ic = i - ab * ICH;
        dst[i] = __float2bfloat16(sm[ic * 9 + ab]);
    }
}

__global__ void w2b_k(const float* __restrict__ w2) {
    int i = blockIdx.x * blockDim.x + threadIdx.x;
    if (i < OC2 * K2) g_W2b[i] = __float2bfloat16(w2[i]);
}

// ---------------- bf16 mma.sync GEMM:  C[n][m] = sum_k A[m][k]*B[n][k] ----------------
// 128x128 block tile, BK=32, 256 threads (8 warps: 4 m x 2 n), double-buffered cp.async.
#define RSTRIDE 80   // smem row pitch in bytes (40 bf16) -> conflict-free ldmatrix

__global__ __launch_bounds__(256) void gemm_bf16(
    const __nv_bfloat16* __restrict__ A, const __nv_bfloat16* __restrict__ B,
    float* __restrict__ C, int ldk, int ktiles, int ldC, int zstride)
{
    __shared__ __align__(128) char smem_raw[2 * 2 * 128 * RSTRIDE];  // 40960 B
    const uint32_t sbase = smem_u32(smem_raw);
    const int tid = threadIdx.x;
    const int lane = tid & 31, wid = tid >> 5;
    const int wm = wid & 3, wn = wid >> 2;
    const int m0 = blockIdx.x * 128, n0 = blockIdx.y * 128;
    const int kofs = blockIdx.z * ktiles * 32;
    C += (size_t)blockIdx.z * zstride;

    float acc[2][8][4];
#pragma unroll
    for (int i = 0; i < 2; i++)
#pragma unroll
        for (int j = 0; j < 8; j++)
#pragma unroll
            for (int q = 0; q < 4; q++) acc[i][j][q] = 0.f;

    auto load_tile = [&](int buf, int t) {
        uint32_t s = sbase + buf * 20480;
        int k = kofs + t * 32;
#pragma unroll
        for (int i = 0; i < 4; i++) {
            int ch = tid + i * 256;        // 0..1023 (A: 0..511, B: 512..1023)
            int half = ch >> 9;
            int row = (ch >> 2) & 127;
            int c4 = ch & 3;
            uint32_t dst = s + half * 10240 + row * RSTRIDE + c4 * 16;
            const __nv_bfloat16* src =
                (half ? B + (size_t)(n0 + row) * ldk : A + (size_t)(m0 + row) * ldk)
                + k + c4 * 8;
            cpasync16(dst, src);
        }
    };

    load_tile(0, 0);
    CP_COMMIT();
    load_tile(1, 1);
    CP_COMMIT();

    const uint32_t rsel = lane & 15;
    const uint32_t chi = (lane >> 4) * 16;

    for (int t = 0; t < ktiles; t++) {
        if (t + 1 < ktiles)
            asm volatile("cp.async.wait_group 1;\n" ::: "memory");
        else
            asm volatile("cp.async.wait_group 0;\n" ::: "memory");
        __syncthreads();

        int buf = t & 1;
        uint32_t sA = sbase + buf * 20480;
        uint32_t sB = sA + 10240;

#pragma unroll
        for (int ks = 0; ks < 2; ks++) {
            uint32_t colB = ks * 32 + chi;
            uint32_t aF[2][4];
#pragma unroll
            for (int mt = 0; mt < 2; mt++) {
                uint32_t addr = sA + (wm * 32 + mt * 16 + rsel) * RSTRIDE + colB;
                ldsm_x4(aF[mt][0], aF[mt][1], aF[mt][2], aF[mt][3], addr);
            }
            uint32_t bF[8][2];
#pragma unroll
            for (int p = 0; p < 4; p++) {
                uint32_t r0, r1, r2, r3;
                uint32_t addr = sB + (wn * 64 + p * 16 + rsel) * RSTRIDE + colB;
                ldsm_x4(r0, r1, r2, r3, addr);
                bF[2 * p][0] = r0; bF[2 * p][1] = r2;
                bF[2 * p + 1][0] = r1; bF[2 * p + 1][1] = r3;
            }
#pragma unroll
            for (int mt = 0; mt < 2; mt++)
#pragma unroll
                for (int nt = 0; nt < 8; nt++)
                    mma_bf16(acc[mt][nt], aF[mt], bF[nt]);
        }
        __syncthreads();
        if (t + 2 < ktiles) {
            load_tile(buf, t + 2);
            CP_COMMIT();
        }
    }

    const int mrow = lane >> 2, ncol = (lane & 3) * 2;
#pragma unroll
    for (int mt = 0; mt < 2; mt++)
#pragma unroll
        for (int nt = 0; nt < 8; nt++) {
            int m = m0 + wm * 32 + mt * 16 + mrow;
            int n = n0 + wn * 64 + nt * 8 + ncol;
            C[(size_t)n * ldC + m]           = acc[mt][nt][0];
            C[(size_t)(n + 1) * ldC + m]     = acc[mt][nt][1];
            C[(size_t)n * ldC + m + 8]       = acc[mt][nt][2];
            C[(size_t)(n + 1) * ldC + m + 8] = acc[mt][nt][3];
        }
}

// ---------------- sparse per-label box-sum accumulation -> g_Tbb[bl][k] ----------------
__global__ __launch_bounds__(512) void acc_kernel(const float* __restrict__ b1) {
    const int bl = blockIdx.x;
    const int b = bl / NL;
    const int l = bl % NL;
    const int oc1 = threadIdx.x;

    __shared__ int msh[NPIX];
    for (int i = threadIdx.x; i < NPIX; i += 512) msh[i] = g_m[b * NPIX + i];
    __syncthreads();

    const int lo[3][3] = {{0, 0, 1}, {0, 0, 1}, {3, 4, 5}};
    const int hi[3][3] = {{18, 19, 20}, {22, 23, 23}, {22, 23, 23}};

    float T9[9];
#pragma unroll
    for (int k = 0; k < 9; k++) T9[k] = 0.f;

    for (int pix = 0; pix < NPIX; pix++) {
        if (msh[pix] != l) continue;
        const float* v = &g_P1[(size_t)(b * NPIX + pix) * M1 + oc1 * 9];
        float vv[9];
#pragma unroll
        for (int t = 0; t < 9; t++) vv[t] = v[t];
        int p = pix / 24, q = pix % 24;

        float rs[3][3];
#pragma unroll
        for (int dr = 0; dr < 3; dr++)
#pragma unroll
            for (int bb = 0; bb < 3; bb++) {
                float s = 0.f;
#pragma unroll
                for (int a = 0; a < 3; a++)
                    if (p >= lo[dr][a] && p <= hi[dr][a]) s += vv[a * 3 + bb];
                rs[dr][bb] = s;
            }
#pragma unroll
        for (int dr = 0; dr < 3; dr++)
#pragma unroll
            for (int dc = 0; dc < 3; dc++) {
                float s = 0.f;
#pragma unroll
                for (int bb = 0; bb < 3; bb++)
                    if (q >= lo[dc][bb] && q <= hi[dc][bb]) s += rs[dr][bb];
                T9[dr * 3 + dc] += s;
            }
    }

    const float nrc[3] = {20.f, 24.f, 20.f};
    float bb1 = b1[oc1];
#pragma unroll
    for (int k = 0; k < 9; k++) {
        float t = (T9[k] + nrc[k / 3] * nrc[k % 3] * bb1) * (1.0f / 576.0f);
        g_Tbb[(size_t)bl * K2 + oc1 * 9 + k] = __float2bfloat16(t);
    }
}

// ---------------- split-K reduce + bias ----------------
__global__ void reduce_k(const float* __restrict__ b2) {
    int i = blockIdx.x * blockDim.x + threadIdx.x;
    if (i >= NPAD * OC2) return;
    const int S = NPAD * OC2;
    float s = 0.f;
#pragma unroll
    for (int z = 0; z < KSPLIT; z++) s += g_part[i + z * S];
    g_out512[i] = s + b2[i & 511];
}

// ---------------- final expansion (float4) ----------------
__global__ void expand_k(const float* __restrict__ w3, const float* __restrict__ b3,
                         float4* __restrict__ out) {
    int i4 = blockIdx.x * blockDim.x + threadIdx.x;
    if (i4 >= TXT_ELEMS / 4) return;
    int c4 = i4 & 127;
    int r = i4 >> 7;
    int l = r % NL;
    int r2 = r / NL;
    int o = r2 % 77;
    int b = r2 / 77;
    float w = __ldg(&w3[o]), bb = __ldg(&b3[o]);
    const float4 v = *(const float4*)&g_out512[((size_t)(b * NL + l) * OC2) + c4 * 4];
    out[i4] = make_float4(w * v.x + bb, w * v.y + bb, w * v.z + bb, w * v.w + bb);
}

// ---------------- launch ----------------
extern "C" void kernel_launch(void* const* d_in, const int* in_sizes, int n_in,
                              void* d_out, int out_size) {
    const float* noise   = (const float*)d_in[0];
    const int*   targets = (const int*)  d_in[1];
    const float* w1      = (const float*)d_in[2];
    const float* b1      = (const float*)d_in[3];
    const float* w2      = (const float*)d_in[4];
    const float* b2      = (const float*)d_in[5];
    const float* w3      = (const float*)d_in[6];
    const float* b3      = (const float*)d_in[7];
    float* out      = (float*)d_out;
    float* out_img  = out;
    float* out_text = out + IMG_ELEMS;

    __nv_bfloat16 *pA1, *pBx, *pW2, *pTb;
    float *pP1, *pPart;
    cudaGetSymbolAddress((void**)&pA1,   g_A1b);
    cudaGetSymbolAddress((void**)&pBx,   g_Bxb);
    cudaGetSymbolAddress((void**)&pW2,   g_W2b);
    cudaGetSymbolAddress((void**)&pTb,   g_Tbb);
    cudaGetSymbolAddress((void**)&pP1,   g_P1);
    cudaGetSymbolAddress((void**)&pPart, g_part);

    // prep
    labels_k<<<2, 576>>>(targets);
    xpack_k<<<dim3(18, 24, 2), dim3(32, 8)>>>(noise);
    w1r_k<<<512, 256>>>(w1);
    w2b_k<<<(OC2 * K2 + 1023) / 1024, 1024>>>(w2);
    img_tr_k<<<dim3(19, 24, 2), dim3(32, 8)>>>(noise, out_img);

    // GEMM1: P1[n][m] = sum_ic A1b[m][ic] * Bxb[n][ic]   (1152 x 4608 x 768)
    gemm_bf16<<<dim3(M1 / 128, N1 / 128, 1), 256>>>(pA1, pBx, pP1, K1, K1 / 32, M1, 0);

    // sparse accumulation -> Tbb[bl][k]
    acc_kernel<<<NBL, 512>>>(b1);

    // GEMM2 split-K: part[z][bl][oc2] = sum_{k chunk z} w2b[oc2][k] * Tbb[bl][k]
    gemm_bf16<<<dim3(OC2 / 128, NPAD / 128, KSPLIT), 256>>>(
        pW2, pTb, pPart, K2, K2 / KSPLIT / 32, OC2, NPAD * OC2);
    reduce_k<<<(NPAD * OC2 + 255) / 256, 256>>>(b2);

    expand_k<<<(TXT_ELEMS / 4 + 255) / 256, 256>>>(w3, b3, (float4*)out_text);
}

// round 4
// speedup vs baseline: 4.6266x; 1.1604x over previous
#include <cuda_runtime.h>
#include <cuda_bf16.h>
#include <cstdint>

// ---------------- problem constants ----------------
#define B_      2
#define NPIX    576
#define NL      171
#define NBL     342
#define NPAD    384          // padded N for GEMM2 (3 x 128)
#define ICH     768
#define OC1     512
#define OC2     512
#define M1      4608         // OC1*9
#define N1      1152         // B_*NPIX
#define K1      768
#define K2      4608
#define KSPLIT  12
#define IMG_ELEMS  (577*B_*768)
#define TXT_ELEMS  (B_*77*NL*512)

// ---------------- scratch (device globals; zero-initialized at load) ----------------
__device__ __align__(128) __nv_bfloat16 g_A1b[M1 * K1];   // w1 rearranged [m=oc1*9+ab][ic]
__device__ __align__(128) __nv_bfloat16 g_Bxb[N1 * K1];   // x transposed  [n][ic]
__device__ __align__(128) float         g_P1[(size_t)N1 * M1];
__device__ __align__(128) __nv_bfloat16 g_W2b[OC2 * K2];  // w2 cast (already K-major)
__device__ __align__(128) __nv_bfloat16 g_Tbb[NPAD * K2]; // [bl][k]; rows >=342 stay zero
__device__ __align__(128) float         g_part[KSPLIT * NPAD * OC2];
__device__ __align__(128) float         g_out512[NPAD * OC2];
__device__ int g_m[N1];

// ---------------- PTX helpers (sm_80 base-target features only) ----------------
__device__ __forceinline__ uint32_t smem_u32(const void* p) {
    uint32_t a;
    asm("{ .reg .u64 t; cvta.to.shared.u64 t, %1; cvt.u32.u64 %0, t; }" : "=r"(a) : "l"(p));
    return a;
}
__device__ __forceinline__ void cpasync16(uint32_t dst, const void* src) {
    asm volatile("cp.async.cg.shared.global [%0], [%1], 16;\n" :: "r"(dst), "l"(src));
}
#define CP_COMMIT() asm volatile("cp.async.commit_group;\n" ::: "memory")

__device__ __forceinline__ void ldsm_x4(uint32_t& r0, uint32_t& r1, uint32_t& r2,
                                        uint32_t& r3, uint32_t addr) {
    asm volatile("ldmatrix.sync.aligned.m8n8.x4.shared.b16 {%0,%1,%2,%3}, [%4];"
                 : "=r"(r0), "=r"(r1), "=r"(r2), "=r"(r3) : "r"(addr));
}
__device__ __forceinline__ void mma_bf16(float* c, const uint32_t* a, const uint32_t* b) {
    asm volatile("mma.sync.aligned.m16n8k16.row.col.f32.bf16.bf16.f32 "
                 "{%0,%1,%2,%3}, {%4,%5,%6,%7}, {%8,%9}, {%0,%1,%2,%3};"
                 : "+f"(c[0]), "+f"(c[1]), "+f"(c[2]), "+f"(c[3])
                 : "r"(a[0]), "r"(a[1]), "r"(a[2]), "r"(a[3]), "r"(b[0]), "r"(b[1]));
}

// ---------------- prep kernels ----------------
__global__ void labels_k(const int* __restrict__ targets) {
    int i = blockIdx.x * blockDim.x + threadIdx.x;
    if (i >= N1) return;
    int b = i / NPIX, pix = i % NPIX;
    int pi = pix / 24, qj = pix % 24;
    g_m[i] = targets[b * 147456 + (pi * 16) * 384 + qj * 16];
}

// image_noise = transpose: out[s][b][c] = noise[b][c][s]
__global__ void img_tr_k(const float* __restrict__ noise, float* __restrict__ out) {
    __shared__ float tile[32][33];
    int b = blockIdx.z;
    int s0 = blockIdx.x * 32, c0 = blockIdx.y * 32;
    int tx = threadIdx.x, ty = threadIdx.y;
    for (int r = ty; r < 32; r += 8) {
        int s = s0 + tx;
        if (s < 577) tile[r][tx] = noise[(size_t)b * 443136 + (c0 + r) * 577 + s];
    }
    __syncthreads();
    for (int r = ty; r < 32; r += 8) {
        int s = s0 + r;
        if (s < 577) out[(size_t)s * (B_ * 768) + b * 768 + c0 + tx] = tile[tx][r];
    }
}

// g_Bxb[(b*576+pix)][ic] = bf16(noise[b][ic][1+pix])
__global__ void xpack_k(const float* __restrict__ noise) {
    __shared__ float tile[32][33];
    int b = blockIdx.z;
    int p0 = blockIdx.x * 32, c0 = blockIdx.y * 32;
    int tx = threadIdx.x, ty = threadIdx.y;
    for (int r = ty; r < 32; r += 8)
        tile[r][tx] = noise[(size_t)b * 443136 + (c0 + r) * 577 + 1 + p0 + tx];
    __syncthreads();
    for (int r = ty; r < 32; r += 8)
        g_Bxb[(size_t)(b * NPIX + p0 + r) * ICH + c0 + tx] = __float2bfloat16(tile[tx][r]);
}

// g_A1b[(oc1*9+ab)][ic] = bf16(w1[oc1][ic][ab])  -- vectorized 4-wide packed stores
__global__ __launch_bounds__(256) void w1r_k(const float* __restrict__ w1) {
    __shared__ float sm[ICH * 9];
    int oc1 = blockIdx.x;
    const float4* src = (const float4*)(w1 + (size_t)oc1 * ICH * 9);
    for (int i = threadIdx.x; i < ICH * 9 / 4; i += 256)
        ((float4*)sm)[i] = src[i];
    __syncthreads();
    uint32_t* dst = (uint32_t*)(g_A1b + (size_t)oc1 * 9 * K1);
    // j2 indexes pairs of output elements: out[ab*768 + ic] = sm[ic*9+ab]
    for (int j2 = threadIdx.x; j2 < ICH * 9 / 2; j2 += 256) {
        int j = j2 * 2;
        int ab = j / ICH, ic = j - ab * ICH;
        __nv_bfloat162 v;
        v.x = __float2bfloat16(sm[ic * 9 + ab]);
        v.y = __float2bfloat16(sm[(ic + 1) * 9 + ab]);
        dst[j2] = *(uint32_t*)&v;
    }
}

// w2 cast, vectorized: 4 floats -> 4 bf16 per thread
__global__ void w2b_k(const float4* __restrict__ w2) {
    int i = blockIdx.x * blockDim.x + threadIdx.x;
    if (i >= OC2 * K2 / 4) return;
    float4 v = w2[i];
    __nv_bfloat162 lo, hi;
    lo.x = __float2bfloat16(v.x); lo.y = __float2bfloat16(v.y);
    hi.x = __float2bfloat16(v.z); hi.y = __float2bfloat16(v.w);
    uint2 o;
    o.x = *(uint32_t*)&lo; o.y = *(uint32_t*)&hi;
    ((uint2*)g_W2b)[i] = o;
}

// ---------------- bf16 mma.sync GEMM:  C[n][m] = sum_k A[m][k]*B[n][k] ----------------
// 128x128 block tile, BK=64, 256 threads (8 warps: 4 m x 2 n), double-buffered cp.async.
#define RSTRIDE 144   // smem row pitch bytes (64 bf16 + 16B pad) -> conflict-free ldmatrix
#define BUFSZ   (2 * 128 * RSTRIDE)   // 36864 per stage (A half + B half)
#define SMEM_SZ (2 * BUFSZ)           // 73728

__global__ __launch_bounds__(256, 2) void gemm_bf16(
    const __nv_bfloat16* __restrict__ A, const __nv_bfloat16* __restrict__ B,
    float* __restrict__ C, int ldk, int ktiles, int ldC, int zstride)
{
    extern __shared__ __align__(128) char smem_raw[];
    const uint32_t sbase = smem_u32(smem_raw);
    const int tid = threadIdx.x;
    const int lane = tid & 31, wid = tid >> 5;
    const int wm = wid & 3, wn = wid >> 2;
    const int m0 = blockIdx.x * 128, n0 = blockIdx.y * 128;
    const int kofs = blockIdx.z * ktiles * 64;
    C += (size_t)blockIdx.z * zstride;

    float acc[2][8][4];
#pragma unroll
    for (int i = 0; i < 2; i++)
#pragma unroll
        for (int j = 0; j < 8; j++)
#pragma unroll
            for (int q = 0; q < 4; q++) acc[i][j][q] = 0.f;

    auto load_tile = [&](int buf, int t) {
        uint32_t s = sbase + buf * BUFSZ;
        int k = kofs + t * 64;
#pragma unroll
        for (int i = 0; i < 8; i++) {
            int ch = tid + i * 256;        // 0..2047 (A: 0..1023, B: 1024..2047)
            int half = ch >> 10;
            int row = (ch >> 3) & 127;
            int c8 = ch & 7;
            uint32_t dst = s + half * (128 * RSTRIDE) + row * RSTRIDE + c8 * 16;
            const __nv_bfloat16* src =
                (half ? B + (size_t)(n0 + row) * ldk : A + (size_t)(m0 + row) * ldk)
                + k + c8 * 8;
            cpasync16(dst, src);
        }
    };

    load_tile(0, 0);
    CP_COMMIT();
    if (ktiles > 1) { load_tile(1, 1); }
    CP_COMMIT();

    const uint32_t rsel = lane & 15;
    const uint32_t chi = (lane >> 4) * 16;

    for (int t = 0; t < ktiles; t++) {
        if (t + 1 < ktiles)
            asm volatile("cp.async.wait_group 1;\n" ::: "memory");
        else
            asm volatile("cp.async.wait_group 0;\n" ::: "memory");
        __syncthreads();

        int buf = t & 1;
        uint32_t sA = sbase + buf * BUFSZ;
        uint32_t sB = sA + 128 * RSTRIDE;

#pragma unroll
        for (int ks = 0; ks < 4; ks++) {
            uint32_t colB = ks * 32 + chi;
            uint32_t aF[2][4];
#pragma unroll
            for (int mt = 0; mt < 2; mt++) {
                uint32_t addr = sA + (wm * 32 + mt * 16 + rsel) * RSTRIDE + colB;
                ldsm_x4(aF[mt][0], aF[mt][1], aF[mt][2], aF[mt][3], addr);
            }
            uint32_t bF[8][2];
#pragma unroll
            for (int p = 0; p < 4; p++) {
                uint32_t r0, r1, r2, r3;
                uint32_t addr = sB + (wn * 64 + p * 16 + rsel) * RSTRIDE + colB;
                ldsm_x4(r0, r1, r2, r3, addr);
                bF[2 * p][0] = r0; bF[2 * p][1] = r2;
                bF[2 * p + 1][0] = r1; bF[2 * p + 1][1] = r3;
            }
#pragma unroll
            for (int mt = 0; mt < 2; mt++)
#pragma unroll
                for (int nt = 0; nt < 8; nt++)
                    mma_bf16(acc[mt][nt], aF[mt], bF[nt]);
        }
        __syncthreads();
        if (t + 2 < ktiles) {
            load_tile(buf, t + 2);
            CP_COMMIT();
        }
    }

    const int mrow = lane >> 2, ncol = (lane & 3) * 2;
#pragma unroll
    for (int mt = 0; mt < 2; mt++)
#pragma unroll
        for (int nt = 0; nt < 8; nt++) {
            int m = m0 + wm * 32 + mt * 16 + mrow;
            int n = n0 + wn * 64 + nt * 8 + ncol;
            C[(size_t)n * ldC + m]           = acc[mt][nt][0];
            C[(size_t)(n + 1) * ldC + m]     = acc[mt][nt][1];
            C[(size_t)n * ldC + m + 8]       = acc[mt][nt][2];
            C[(size_t)(n + 1) * ldC + m + 8] = acc[mt][nt][3];
        }
}

// ---------------- sparse per-label box-sum accumulation -> g_Tbb[bl][k] ----------------
__global__ __launch_bounds__(512) void acc_kernel(const float* __restrict__ b1) {
    const int bl = blockIdx.x;
    const int b = bl / NL;
    const int l = bl % NL;
    const int oc1 = threadIdx.x;

    __shared__ int msh[NPIX];
    for (int i = threadIdx.x; i < NPIX; i += 512) msh[i] = g_m[b * NPIX + i];
    __syncthreads();

    const int lo[3][3] = {{0, 0, 1}, {0, 0, 1}, {3, 4, 5}};
    const int hi[3][3] = {{18, 19, 20}, {22, 23, 23}, {22, 23, 23}};

    float T9[9];
#pragma unroll
    for (int k = 0; k < 9; k++) T9[k] = 0.f;

    for (int pix = 0; pix < NPIX; pix++) {
        if (msh[pix] != l) continue;
        const float* v = &g_P1[(size_t)(b * NPIX + pix) * M1 + oc1 * 9];
        float vv[9];
#pragma unroll
        for (int t = 0; t < 9; t++) vv[t] = v[t];
        int p = pix / 24, q = pix % 24;

        float rs[3][3];
#pragma unroll
        for (int dr = 0; dr < 3; dr++)
#pragma unroll
            for (int bb = 0; bb < 3; bb++) {
                float s = 0.f;
#pragma unroll
                for (int a = 0; a < 3; a++)
                    if (p >= lo[dr][a] && p <= hi[dr][a]) s += vv[a * 3 + bb];
                rs[dr][bb] = s;
            }
#pragma unroll
        for (int dr = 0; dr < 3; dr++)
#pragma unroll
            for (int dc = 0; dc < 3; dc++) {
                float s = 0.f;
#pragma unroll
                for (int bb = 0; bb < 3; bb++)
                    if (q >= lo[dc][bb] && q <= hi[dc][bb]) s += rs[dr][bb];
                T9[dr * 3 + dc] += s;
            }
    }

    const float nrc[3] = {20.f, 24.f, 20.f};
    float bb1 = b1[oc1];
#pragma unroll
    for (int k = 0; k < 9; k++) {
        float t = (T9[k] + nrc[k / 3] * nrc[k % 3] * bb1) * (1.0f / 576.0f);
        g_Tbb[(size_t)bl * K2 + oc1 * 9 + k] = __float2bfloat16(t);
    }
}

// ---------------- split-K reduce + bias ----------------
__global__ void reduce_k(const float* __restrict__ b2) {
    int i = blockIdx.x * blockDim.x + threadIdx.x;
    if (i >= NPAD * OC2) return;
    const int S = NPAD * OC2;
    float s = 0.f;
#pragma unroll
    for (int z = 0; z < KSPLIT; z++) s += g_part[i + z * S];
    g_out512[i] = s + b2[i & 511];
}

// ---------------- final expansion (float4) ----------------
__global__ void expand_k(const float* __restrict__ w3, const float* __restrict__ b3,
                         float4* __restrict__ out) {
    int i4 = blockIdx.x * blockDim.x + threadIdx.x;
    if (i4 >= TXT_ELEMS / 4) return;
    int c4 = i4 & 127;
    int r = i4 >> 7;
    int l = r % NL;
    int r2 = r / NL;
    int o = r2 % 77;
    int b = r2 / 77;
    float w = __ldg(&w3[o]), bb = __ldg(&b3[o]);
    const float4 v = *(const float4*)&g_out512[((size_t)(b * NL + l) * OC2) + c4 * 4];
    out[i4] = make_float4(w * v.x + bb, w * v.y + bb, w * v.z + bb, w * v.w + bb);
}

// ---------------- launch ----------------
extern "C" void kernel_launch(void* const* d_in, const int* in_sizes, int n_in,
                              void* d_out, int out_size) {
    const float* noise   = (const float*)d_in[0];
    const int*   targets = (const int*)  d_in[1];
    const float* w1      = (const float*)d_in[2];
    const float* b1      = (const float*)d_in[3];
    const float* w2      = (const float*)d_in[4];
    const float* b2      = (const float*)d_in[5];
    const float* w3      = (const float*)d_in[6];
    const float* b3      = (const float*)d_in[7];
    float* out      = (float*)d_out;
    float* out_img  = out;
    float* out_text = out + IMG_ELEMS;

    __nv_bfloat16 *pA1, *pBx, *pW2, *pTb;
    float *pP1, *pPart;
    cudaGetSymbolAddress((void**)&pA1,   g_A1b);
    cudaGetSymbolAddress((void**)&pBx,   g_Bxb);
    cudaGetSymbolAddress((void**)&pW2,   g_W2b);
    cudaGetSymbolAddress((void**)&pTb,   g_Tbb);
    cudaGetSymbolAddress((void**)&pP1,   g_P1);
    cudaGetSymbolAddress((void**)&pPart, g_part);

    cudaFuncSetAttribute(gemm_bf16, cudaFuncAttributeMaxDynamicSharedMemorySize, SMEM_SZ);

    // prep
    labels_k<<<2, 576>>>(targets);
    xpack_k<<<dim3(18, 24, 2), dim3(32, 8)>>>(noise);
    w1r_k<<<512, 256>>>(w1);
    w2b_k<<<(OC2 * K2 / 4 + 255) / 256, 256>>>((const float4*)w2);
    img_tr_k<<<dim3(19, 24, 2), dim3(32, 8)>>>(noise, out_img);

    // GEMM1: P1[n][m] = sum_ic A1b[m][ic] * Bxb[n][ic]   (1152 x 4608 x 768)
    gemm_bf16<<<dim3(M1 / 128, N1 / 128, 1), 256, SMEM_SZ>>>(pA1, pBx, pP1, K1, K1 / 64, M1, 0);

    // sparse accumulation -> Tbb[bl][k]
    acc_kernel<<<NBL, 512>>>(b1);

    // GEMM2 split-K: part[z][bl][oc2] = sum_{k chunk z} w2b[oc2][k] * Tbb[bl][k]
    gemm_bf16<<<dim3(OC2 / 128, NPAD / 128, KSPLIT), 256, SMEM_SZ>>>(
        pW2, pTb, pPart, K2, K2 / KSPLIT / 64, OC2, NPAD * OC2);
    reduce_k<<<(NPAD * OC2 + 255) / 256, 256>>>(b2);

    expand_k<<<(TXT_ELEMS / 4 + 255) / 256, 256>>>(w3, b3, (float4*)out_text);
}

// round 5
// speedup vs baseline: 4.7000x; 1.0159x over previous
#include <cuda_runtime.h>
#include <cuda_bf16.h>
#include <cstdint>

// ---------------- problem constants ----------------
#define B_      2
#define NPIX    576
#define NL      171
#define NBL     342
#define NPAD    384          // padded N for GEMM2 (3 x 128)
#define ICH     768
#define OC1     512
#define OC2     512
#define M1      4608         // OC1*9
#define N1      1152         // B_*NPIX
#define K1      768
#define K2      4608
#define KSPLIT  12
#define IMG_ELEMS  (577*B_*768)
#define TXT_ELEMS  (B_*77*NL*512)

// ---------------- scratch (device globals; zero-initialized at load) ----------------
__device__ __align__(128) __nv_bfloat16 g_A1b[M1 * K1];   // w1 rearranged [m=oc1*9+ab][ic]
__device__ __align__(128) __nv_bfloat16 g_Bxb[N1 * K1];   // x transposed  [n][ic]
__device__ __align__(128) float         g_P1[(size_t)N1 * M1];
__device__ __align__(128) __nv_bfloat16 g_W2b[OC2 * K2];  // w2 cast (already K-major)
__device__ __align__(128) __nv_bfloat16 g_Tbb[NPAD * K2]; // [bl][k]; rows >=342 stay zero
__device__ __align__(128) float         g_part[KSPLIT * NPAD * OC2];
__device__ __align__(128) float         g_out512[NPAD * OC2];
__device__ int g_m[N1];

// ---------------- PTX helpers (sm_80 base-target features only) ----------------
__device__ __forceinline__ uint32_t smem_u32(const void* p) {
    uint32_t a;
    asm("{ .reg .u64 t; cvta.to.shared.u64 t, %1; cvt.u32.u64 %0, t; }" : "=r"(a) : "l"(p));
    return a;
}
__device__ __forceinline__ void cpasync16(uint32_t dst, const void* src) {
    asm volatile("cp.async.cg.shared.global [%0], [%1], 16;\n" :: "r"(dst), "l"(src));
}
#define CP_COMMIT() asm volatile("cp.async.commit_group;\n" ::: "memory")

__device__ __forceinline__ void ldsm_x4(uint32_t& r0, uint32_t& r1, uint32_t& r2,
                                        uint32_t& r3, uint32_t addr) {
    asm volatile("ldmatrix.sync.aligned.m8n8.x4.shared.b16 {%0,%1,%2,%3}, [%4];"
                 : "=r"(r0), "=r"(r1), "=r"(r2), "=r"(r3) : "r"(addr));
}
__device__ __forceinline__ void mma_bf16(float* c, const uint32_t* a, const uint32_t* b) {
    asm volatile("mma.sync.aligned.m16n8k16.row.col.f32.bf16.bf16.f32 "
                 "{%0,%1,%2,%3}, {%4,%5,%6,%7}, {%8,%9}, {%0,%1,%2,%3};"
                 : "+f"(c[0]), "+f"(c[1]), "+f"(c[2]), "+f"(c[3])
                 : "r"(a[0]), "r"(a[1]), "r"(a[2]), "r"(a[3]), "r"(b[0]), "r"(b[1]));
}

// ---------------- labels ----------------
__global__ void labels_k(const int* __restrict__ targets) {
    int i = blockIdx.x * blockDim.x + threadIdx.x;
    if (i >= N1) return;
    int b = i / NPIX, pix = i % NPIX;
    int pi = pix / 24, qj = pix % 24;
    g_m[i] = targets[b * 147456 + (pi * 16) * 384 + qj * 16];
}

// ---------------- fused prep A: xpack (864 blocks) + w1r (512 blocks) ----------------
// xpack: g_Bxb[(b*576+pix)][ic] = bf16(noise[b][ic][1+pix])
// w1r:   g_A1b[(oc1*9+ab)][ic] = bf16(w1[oc1][ic][ab])
#define XPACK_BLOCKS (18 * 24 * 2)   // 864
__global__ __launch_bounds__(256) void prepA_k(const float* __restrict__ noise,
                                               const float* __restrict__ w1) {
    int bid = blockIdx.x;
    if (bid < XPACK_BLOCKS) {
        __shared__ float tile[32][33];
        int b = bid / (18 * 24);
        int r0 = bid % (18 * 24);
        int p0 = (r0 % 18) * 32, c0 = (r0 / 18) * 32;
        int tx = threadIdx.x & 31, ty = threadIdx.x >> 5;
        for (int r = ty; r < 32; r += 8)
            tile[r][tx] = noise[(size_t)b * 443136 + (c0 + r) * 577 + 1 + p0 + tx];
        __syncthreads();
        for (int r = ty; r < 32; r += 8)
            g_Bxb[(size_t)(b * NPIX + p0 + r) * ICH + c0 + tx] = __float2bfloat16(tile[tx][r]);
    } else {
        __shared__ float sm[ICH * 9];
        int oc1 = bid - XPACK_BLOCKS;
        const float4* src = (const float4*)(w1 + (size_t)oc1 * ICH * 9);
        for (int i = threadIdx.x; i < ICH * 9 / 4; i += 256)
            ((float4*)sm)[i] = src[i];
        __syncthreads();
        uint32_t* dst = (uint32_t*)(g_A1b + (size_t)oc1 * 9 * K1);
        for (int j2 = threadIdx.x; j2 < ICH * 9 / 2; j2 += 256) {
            int j = j2 * 2;
            int ab = j / ICH, ic = j - ab * ICH;
            __nv_bfloat162 v;
            v.x = __float2bfloat16(sm[ic * 9 + ab]);
            v.y = __float2bfloat16(sm[(ic + 1) * 9 + ab]);
            dst[j2] = *(uint32_t*)&v;
        }
    }
}

// ---------------- fused prep B: w2 cast (2304 blocks) + img transpose (912 blocks) ----------------
#define W2B_BLOCKS 2304
__global__ __launch_bounds__(256) void prepB_k(const float4* __restrict__ w2,
                                               const float* __restrict__ noise,
                                               float* __restrict__ out_img) {
    int bid = blockIdx.x;
    if (bid < W2B_BLOCKS) {
        int i = bid * 256 + threadIdx.x;
        float4 v = w2[i];
        __nv_bfloat162 lo, hi;
        lo.x = __float2bfloat16(v.x); lo.y = __float2bfloat16(v.y);
        hi.x = __float2bfloat16(v.z); hi.y = __float2bfloat16(v.w);
        uint2 o;
        o.x = *(uint32_t*)&lo; o.y = *(uint32_t*)&hi;
        ((uint2*)g_W2b)[i] = o;
    } else {
        __shared__ float tile[32][33];
        int t = bid - W2B_BLOCKS;            // 0..911 = 19*24*2
        int b = t / (19 * 24);
        int r0 = t % (19 * 24);
        int s0 = (r0 % 19) * 32, c0 = (r0 / 19) * 32;
        int tx = threadIdx.x & 31, ty = threadIdx.x >> 5;
        for (int r = ty; r < 32; r += 8) {
            int s = s0 + tx;
            if (s < 577) tile[r][tx] = noise[(size_t)b * 443136 + (c0 + r) * 577 + s];
        }
        __syncthreads();
        for (int r = ty; r < 32; r += 8) {
            int s = s0 + r;
            if (s < 577) out_img[(size_t)s * (B_ * 768) + b * 768 + c0 + tx] = tile[tx][r];
        }
    }
}

// ---------------- bf16 mma.sync GEMM:  C[n][m] = sum_k A[m][k]*B[n][k] ----------------
// 128x128 block tile, BK=64, 256 threads (8 warps: 4 m x 2 n), double-buffered cp.async.
#define RSTRIDE 144   // smem row pitch bytes (64 bf16 + 16B pad) -> conflict-free ldmatrix
#define BUFSZ   (2 * 128 * RSTRIDE)   // 36864 per stage (A half + B half)
#define SMEM_SZ (2 * BUFSZ)           // 73728

__global__ __launch_bounds__(256, 2) void gemm_bf16(
    const __nv_bfloat16* __restrict__ A, const __nv_bfloat16* __restrict__ B,
    float* __restrict__ C, int ldk, int ktiles, int ldC, int zstride)
{
    extern __shared__ __align__(128) char smem_raw[];
    const uint32_t sbase = smem_u32(smem_raw);
    const int tid = threadIdx.x;
    const int lane = tid & 31, wid = tid >> 5;
    const int wm = wid & 3, wn = wid >> 2;
    const int m0 = blockIdx.x * 128, n0 = blockIdx.y * 128;
    const int kofs = blockIdx.z * ktiles * 64;
    C += (size_t)blockIdx.z * zstride;

    float acc[2][8][4];
#pragma unroll
    for (int i = 0; i < 2; i++)
#pragma unroll
        for (int j = 0; j < 8; j++)
#pragma unroll
            for (int q = 0; q < 4; q++) acc[i][j][q] = 0.f;

    auto load_tile = [&](int buf, int t) {
        uint32_t s = sbase + buf * BUFSZ;
        int k = kofs + t * 64;
#pragma unroll
        for (int i = 0; i < 8; i++) {
            int ch = tid + i * 256;        // 0..2047 (A: 0..1023, B: 1024..2047)
            int half = ch >> 10;
            int row = (ch >> 3) & 127;
            int c8 = ch & 7;
            uint32_t dst = s + half * (128 * RSTRIDE) + row * RSTRIDE + c8 * 16;
            const __nv_bfloat16* src =
                (half ? B + (size_t)(n0 + row) * ldk : A + (size_t)(m0 + row) * ldk)
                + k + c8 * 8;
            cpasync16(dst, src);
        }
    };

    load_tile(0, 0);
    CP_COMMIT();
    if (ktiles > 1) { load_tile(1, 1); }
    CP_COMMIT();

    const uint32_t rsel = lane & 15;
    const uint32_t chi = (lane >> 4) * 16;

    for (int t = 0; t < ktiles; t++) {
        if (t + 1 < ktiles)
            asm volatile("cp.async.wait_group 1;\n" ::: "memory");
        else
            asm volatile("cp.async.wait_group 0;\n" ::: "memory");
        __syncthreads();

        int buf = t & 1;
        uint32_t sA = sbase + buf * BUFSZ;
        uint32_t sB = sA + 128 * RSTRIDE;

#pragma unroll
        for (int ks = 0; ks < 4; ks++) {
            uint32_t colB = ks * 32 + chi;
            uint32_t aF[2][4];
#pragma unroll
            for (int mt = 0; mt < 2; mt++) {
                uint32_t addr = sA + (wm * 32 + mt * 16 + rsel) * RSTRIDE + colB;
                ldsm_x4(aF[mt][0], aF[mt][1], aF[mt][2], aF[mt][3], addr);
            }
            uint32_t bF[8][2];
#pragma unroll
            for (int p = 0; p < 4; p++) {
                uint32_t r0, r1, r2, r3;
                uint32_t addr = sB + (wn * 64 + p * 16 + rsel) * RSTRIDE + colB;
                ldsm_x4(r0, r1, r2, r3, addr);
                bF[2 * p][0] = r0; bF[2 * p][1] = r2;
                bF[2 * p + 1][0] = r1; bF[2 * p + 1][1] = r3;
            }
#pragma unroll
            for (int mt = 0; mt < 2; mt++)
#pragma unroll
                for (int nt = 0; nt < 8; nt++)
                    mma_bf16(acc[mt][nt], aF[mt], bF[nt]);
        }
        __syncthreads();
        if (t + 2 < ktiles) {
            load_tile(buf, t + 2);
            CP_COMMIT();
        }
    }

    const int mrow = lane >> 2, ncol = (lane & 3) * 2;
#pragma unroll
    for (int mt = 0; mt < 2; mt++)
#pragma unroll
        for (int nt = 0; nt < 8; nt++) {
            int m = m0 + wm * 32 + mt * 16 + mrow;
            int n = n0 + wn * 64 + nt * 8 + ncol;
            C[(size_t)n * ldC + m]           = acc[mt][nt][0];
            C[(size_t)(n + 1) * ldC + m]     = acc[mt][nt][1];
            C[(size_t)n * ldC + m + 8]       = acc[mt][nt][2];
            C[(size_t)(n + 1) * ldC + m + 8] = acc[mt][nt][3];
        }
}

// ---------------- sparse per-label box-sum accumulation -> g_Tbb[bl][k] ----------------
__global__ __launch_bounds__(512) void acc_kernel(const float* __restrict__ b1) {
    const int bl = blockIdx.x;
    const int b = bl / NL;
    const int l = bl % NL;
    const int oc1 = threadIdx.x;

    __shared__ int msh[NPIX];
    for (int i = threadIdx.x; i < NPIX; i += 512) msh[i] = g_m[b * NPIX + i];
    __syncthreads();

    const int lo[3][3] = {{0, 0, 1}, {0, 0, 1}, {3, 4, 5}};
    const int hi[3][3] = {{18, 19, 20}, {22, 23, 23}, {22, 23, 23}};

    float T9[9];
#pragma unroll
    for (int k = 0; k < 9; k++) T9[k] = 0.f;

    for (int pix = 0; pix < NPIX; pix++) {
        if (msh[pix] != l) continue;
        const float* v = &g_P1[(size_t)(b * NPIX + pix) * M1 + oc1 * 9];
        float vv[9];
#pragma unroll
        for (int t = 0; t < 9; t++) vv[t] = v[t];
        int p = pix / 24, q = pix % 24;

        float rs[3][3];
#pragma unroll
        for (int dr = 0; dr < 3; dr++)
#pragma unroll
            for (int bb = 0; bb < 3; bb++) {
                float s = 0.f;
#pragma unroll
                for (int a = 0; a < 3; a++)
                    if (p >= lo[dr][a] && p <= hi[dr][a]) s += vv[a * 3 + bb];
                rs[dr][bb] = s;
            }
#pragma unroll
        for (int dr = 0; dr < 3; dr++)
#pragma unroll
            for (int dc = 0; dc < 3; dc++) {
                float s = 0.f;
#pragma unroll
                for (int bb = 0; bb < 3; bb++)
                    if (q >= lo[dc][bb] && q <= hi[dc][bb]) s += rs[dr][bb];
                T9[dr * 3 + dc] += s;
            }
    }

    const float nrc[3] = {20.f, 24.f, 20.f};
    float bb1 = b1[oc1];
#pragma unroll
    for (int k = 0; k < 9; k++) {
        float t = (T9[k] + nrc[k / 3] * nrc[k % 3] * bb1) * (1.0f / 576.0f);
        g_Tbb[(size_t)bl * K2 + oc1 * 9 + k] = __float2bfloat16(t);
    }
}

// ---------------- split-K reduce + bias ----------------
__global__ void reduce_k(const float* __restrict__ b2) {
    int i = blockIdx.x * blockDim.x + threadIdx.x;
    if (i >= NPAD * OC2) return;
    const int S = NPAD * OC2;
    float s = 0.f;
#pragma unroll
    for (int z = 0; z < KSPLIT; z++) s += g_part[i + z * S];
    g_out512[i] = s + b2[i & 511];
}

// ---------------- final expansion (float4) ----------------
__global__ void expand_k(const float* __restrict__ w3, const float* __restrict__ b3,
                         float4* __restrict__ out) {
    int i4 = blockIdx.x * blockDim.x + threadIdx.x;
    if (i4 >= TXT_ELEMS / 4) return;
    int c4 = i4 & 127;
    int r = i4 >> 7;
    int l = r % NL;
    int r2 = r / NL;
    int o = r2 % 77;
    int b = r2 / 77;
    float w = __ldg(&w3[o]), bb = __ldg(&b3[o]);
    const float4 v = *(const float4*)&g_out512[((size_t)(b * NL + l) * OC2) + c4 * 4];
    out[i4] = make_float4(w * v.x + bb, w * v.y + bb, w * v.z + bb, w * v.w + bb);
}

// ---------------- launch ----------------
extern "C" void kernel_launch(void* const* d_in, const int* in_sizes, int n_in,
                              void* d_out, int out_size) {
    const float* noise   = (const float*)d_in[0];
    const int*   targets = (const int*)  d_in[1];
    const float* w1      = (const float*)d_in[2];
    const float* b1      = (const float*)d_in[3];
    const float* w2      = (const float*)d_in[4];
    const float* b2      = (const float*)d_in[5];
    const float* w3      = (const float*)d_in[6];
    const float* b3      = (const float*)d_in[7];
    float* out      = (float*)d_out;
    float* out_img  = out;
    float* out_text = out + IMG_ELEMS;

    __nv_bfloat16 *pA1, *pBx, *pW2, *pTb;
    float *pP1, *pPart;
    cudaGetSymbolAddress((void**)&pA1,   g_A1b);
    cudaGetSymbolAddress((void**)&pBx,   g_Bxb);
    cudaGetSymbolAddress((void**)&pW2,   g_W2b);
    cudaGetSymbolAddress((void**)&pTb,   g_Tbb);
    cudaGetSymbolAddress((void**)&pP1,   g_P1);
    cudaGetSymbolAddress((void**)&pPart, g_part);

    cudaFuncSetAttribute(gemm_bf16, cudaFuncAttributeMaxDynamicSharedMemorySize, SMEM_SZ);

    // launch order chosen so the 4th launch (ncu -s 5 target) is GEMM1.
    prepA_k<<<XPACK_BLOCKS + 512, 256>>>(noise, w1);                  // 1
    prepB_k<<<W2B_BLOCKS + 912, 256>>>((const float4*)w2, noise, out_img); // 2
    labels_k<<<2, 576>>>(targets);                                    // 3

    // 4: GEMM1: P1[n][m] = sum_ic A1b[m][ic] * Bxb[n][ic]   (1152 x 4608 x 768)
    gemm_bf16<<<dim3(M1 / 128, N1 / 128, 1), 256, SMEM_SZ>>>(pA1, pBx, pP1, K1, K1 / 64, M1, 0);

    // 5: sparse accumulation -> Tbb[bl][k]
    acc_kernel<<<NBL, 512>>>(b1);

    // 6: GEMM2 split-K: part[z][bl][oc2] = sum_{k chunk z} w2b[oc2][k] * Tbb[bl][k]
    gemm_bf16<<<dim3(OC2 / 128, NPAD / 128, KSPLIT), 256, SMEM_SZ>>>(
        pW2, pTb, pPart, K2, K2 / KSPLIT / 64, OC2, NPAD * OC2);
    reduce_k<<<(NPAD * OC2 + 255) / 256, 256>>>(b2);                  // 7

    expand_k<<<(TXT_ELEMS / 4 + 255) / 256, 256>>>(w3, b3, (float4*)out_text); // 8
}

// round 6
// speedup vs baseline: 4.7572x; 1.0122x over previous
#include <cuda_runtime.h>
#include <cuda_bf16.h>
#include <cstdint>

// ---------------- problem constants ----------------
#define B_      2
#define NPIX    576
#define NL      171
#define NBL     342
#define NPAD    384          // padded N for GEMM2 (6 x 64)
#define ICH     768
#define OC1     512
#define OC2     512
#define M1      4608         // OC1*9
#define N1      1152         // B_*NPIX
#define K1      768
#define K2      4608
#define KSPLIT  12
#define IMG_ELEMS  (577*B_*768)
#define TXT_ELEMS  (B_*77*NL*512)

// ---------------- scratch (device globals; zero-initialized at load) ----------------
__device__ __align__(128) __nv_bfloat16 g_A1b[M1 * K1];   // w1 rearranged [m=oc1*9+ab][ic]
__device__ __align__(128) __nv_bfloat16 g_Bxb[N1 * K1];   // x transposed  [n][ic]
__device__ __align__(128) float         g_P1[(size_t)N1 * M1];
__device__ __align__(128) __nv_bfloat16 g_W2b[OC2 * K2];  // w2 cast (already K-major)
__device__ __align__(128) __nv_bfloat16 g_Tbb[NPAD * K2]; // [bl][k]; rows >=342 stay zero
__device__ __align__(128) float         g_part[KSPLIT * NPAD * OC2];
__device__ __align__(128) float         g_out512[NPAD * OC2];
__device__ int g_m[N1];

// ---------------- PTX helpers (sm_80 base-target features only) ----------------
__device__ __forceinline__ uint32_t smem_u32(const void* p) {
    uint32_t a;
    asm("{ .reg .u64 t; cvta.to.shared.u64 t, %1; cvt.u32.u64 %0, t; }" : "=r"(a) : "l"(p));
    return a;
}
__device__ __forceinline__ void cpasync16(uint32_t dst, const void* src) {
    asm volatile("cp.async.cg.shared.global [%0], [%1], 16;\n" :: "r"(dst), "l"(src));
}
#define CP_COMMIT() asm volatile("cp.async.commit_group;\n" ::: "memory")

__device__ __forceinline__ void ldsm_x4(uint32_t& r0, uint32_t& r1, uint32_t& r2,
                                        uint32_t& r3, uint32_t addr) {
    asm volatile("ldmatrix.sync.aligned.m8n8.x4.shared.b16 {%0,%1,%2,%3}, [%4];"
                 : "=r"(r0), "=r"(r1), "=r"(r2), "=r"(r3) : "r"(addr));
}
__device__ __forceinline__ void mma_bf16(float* c, const uint32_t* a, const uint32_t* b) {
    asm volatile("mma.sync.aligned.m16n8k16.row.col.f32.bf16.bf16.f32 "
                 "{%0,%1,%2,%3}, {%4,%5,%6,%7}, {%8,%9}, {%0,%1,%2,%3};"
                 : "+f"(c[0]), "+f"(c[1]), "+f"(c[2]), "+f"(c[3])
                 : "r"(a[0]), "r"(a[1]), "r"(a[2]), "r"(a[3]), "r"(b[0]), "r"(b[1]));
}

// ---------------- labels ----------------
__global__ void labels_k(const int* __restrict__ targets) {
    int i = blockIdx.x * blockDim.x + threadIdx.x;
    if (i >= N1) return;
    int b = i / NPIX, pix = i % NPIX;
    int pi = pix / 24, qj = pix % 24;
    g_m[i] = targets[b * 147456 + (pi * 16) * 384 + qj * 16];
}

// ---------------- fused prep A: xpack (864 blocks) + w1r (512 blocks) ----------------
#define XPACK_BLOCKS (18 * 24 * 2)   // 864
__global__ __launch_bounds__(256) void prepA_k(const float* __restrict__ noise,
                                               const float* __restrict__ w1) {
    int bid = blockIdx.x;
    if (bid < XPACK_BLOCKS) {
        __shared__ float tile[32][33];
        int b = bid / (18 * 24);
        int r0 = bid % (18 * 24);
        int p0 = (r0 % 18) * 32, c0 = (r0 / 18) * 32;
        int tx = threadIdx.x & 31, ty = threadIdx.x >> 5;
        for (int r = ty; r < 32; r += 8)
            tile[r][tx] = noise[(size_t)b * 443136 + (c0 + r) * 577 + 1 + p0 + tx];
        __syncthreads();
        for (int r = ty; r < 32; r += 8)
            g_Bxb[(size_t)(b * NPIX + p0 + r) * ICH + c0 + tx] = __float2bfloat16(tile[tx][r]);
    } else {
        __shared__ float sm[ICH * 9];
        int oc1 = bid - XPACK_BLOCKS;
        const float4* src = (const float4*)(w1 + (size_t)oc1 * ICH * 9);
        for (int i = threadIdx.x; i < ICH * 9 / 4; i += 256)
            ((float4*)sm)[i] = src[i];
        __syncthreads();
        uint32_t* dst = (uint32_t*)(g_A1b + (size_t)oc1 * 9 * K1);
        for (int j2 = threadIdx.x; j2 < ICH * 9 / 2; j2 += 256) {
            int j = j2 * 2;
            int ab = j / ICH, ic = j - ab * ICH;
            __nv_bfloat162 v;
            v.x = __float2bfloat16(sm[ic * 9 + ab]);
            v.y = __float2bfloat16(sm[(ic + 1) * 9 + ab]);
            dst[j2] = *(uint32_t*)&v;
        }
    }
}

// ---------------- fused prep B: w2 cast (2304 blocks) + img transpose (912 blocks) ----------------
#define W2B_BLOCKS 2304
__global__ __launch_bounds__(256) void prepB_k(const float4* __restrict__ w2,
                                               const float* __restrict__ noise,
                                               float* __restrict__ out_img) {
    int bid = blockIdx.x;
    if (bid < W2B_BLOCKS) {
        int i = bid * 256 + threadIdx.x;
        float4 v = w2[i];
        __nv_bfloat162 lo, hi;
        lo.x = __float2bfloat16(v.x); lo.y = __float2bfloat16(v.y);
        hi.x = __float2bfloat16(v.z); hi.y = __float2bfloat16(v.w);
        uint2 o;
        o.x = *(uint32_t*)&lo; o.y = *(uint32_t*)&hi;
        ((uint2*)g_W2b)[i] = o;
    } else {
        __shared__ float tile[32][33];
        int t = bid - W2B_BLOCKS;            // 0..911 = 19*24*2
        int b = t / (19 * 24);
        int r0 = t % (19 * 24);
        int s0 = (r0 % 19) * 32, c0 = (r0 / 19) * 32;
        int tx = threadIdx.x & 31, ty = threadIdx.x >> 5;
        for (int r = ty; r < 32; r += 8) {
            int s = s0 + tx;
            if (s < 577) tile[r][tx] = noise[(size_t)b * 443136 + (c0 + r) * 577 + s];
        }
        __syncthreads();
        for (int r = ty; r < 32; r += 8) {
            int s = s0 + r;
            if (s < 577) out_img[(size_t)s * (B_ * 768) + b * 768 + c0 + tx] = tile[tx][r];
        }
    }
}

// ---------------- bf16 mma.sync GEMM:  C[n][m] = sum_k A[m][k]*B[n][k] ----------------
// 128(M)x64(N) block tile, BK=64, 256 threads (8 warps: 4 m x 2 n), warp tile 32x32,
// double-buffered cp.async. Finer tiles -> 648 CTAs for GEMM1 (better wave fill).
#define RSTRIDE 144   // smem row pitch bytes (64 bf16 + 16B pad) -> conflict-free ldmatrix
#define A_ROWS  128
#define B_ROWS  64
#define BUFSZ   ((A_ROWS + B_ROWS) * RSTRIDE)   // 27648 per stage
#define SMEM_SZ (2 * BUFSZ)                     // 55296

__global__ __launch_bounds__(256) void gemm_bf16(
    const __nv_bfloat16* __restrict__ A, const __nv_bfloat16* __restrict__ B,
    float* __restrict__ C, int ldk, int ktiles, int ldC, int zstride)
{
    extern __shared__ __align__(128) char smem_raw[];
    const uint32_t sbase = smem_u32(smem_raw);
    const int tid = threadIdx.x;
    const int lane = tid & 31, wid = tid >> 5;
    const int wm = wid & 3, wn = wid >> 2;
    const int m0 = blockIdx.x * 128, n0 = blockIdx.y * 64;
    const int kofs = blockIdx.z * ktiles * 64;
    C += (size_t)blockIdx.z * zstride;

    float acc[2][4][4];
#pragma unroll
    for (int i = 0; i < 2; i++)
#pragma unroll
        for (int j = 0; j < 4; j++)
#pragma unroll
            for (int q = 0; q < 4; q++) acc[i][j][q] = 0.f;

    auto load_tile = [&](int buf, int t) {
        uint32_t s = sbase + buf * BUFSZ;
        int k = kofs + t * 64;
#pragma unroll
        for (int i = 0; i < 6; i++) {
            int ch = tid + i * 256;        // 0..1535 (A: 0..1023, B: 1024..1535)
            int isB = ch >> 10;
            int row = (ch >> 3) & (isB ? 63 : 127);
            int c8 = ch & 7;
            uint32_t dst = s + isB * (A_ROWS * RSTRIDE) + row * RSTRIDE + c8 * 16;
            const __nv_bfloat16* src =
                (isB ? B + (size_t)(n0 + row) * ldk : A + (size_t)(m0 + row) * ldk)
                + k + c8 * 8;
            cpasync16(dst, src);
        }
    };

    load_tile(0, 0);
    CP_COMMIT();
    if (ktiles > 1) { load_tile(1, 1); }
    CP_COMMIT();

    const uint32_t rsel = lane & 15;
    const uint32_t chi = (lane >> 4) * 16;

    for (int t = 0; t < ktiles; t++) {
        if (t + 1 < ktiles)
            asm volatile("cp.async.wait_group 1;\n" ::: "memory");
        else
            asm volatile("cp.async.wait_group 0;\n" ::: "memory");
        __syncthreads();

        int buf = t & 1;
        uint32_t sA = sbase + buf * BUFSZ;
        uint32_t sB = sA + A_ROWS * RSTRIDE;

#pragma unroll
        for (int ks = 0; ks < 4; ks++) {
            uint32_t colB = ks * 32 + chi;
            uint32_t aF[2][4];
#pragma unroll
            for (int mt = 0; mt < 2; mt++) {
                uint32_t addr = sA + (wm * 32 + mt * 16 + rsel) * RSTRIDE + colB;
                ldsm_x4(aF[mt][0], aF[mt][1], aF[mt][2], aF[mt][3], addr);
            }
            uint32_t bF[4][2];
#pragma unroll
            for (int p = 0; p < 2; p++) {
                uint32_t r0, r1, r2, r3;
                uint32_t addr = sB + (wn * 32 + p * 16 + rsel) * RSTRIDE + colB;
                ldsm_x4(r0, r1, r2, r3, addr);
                bF[2 * p][0] = r0; bF[2 * p][1] = r2;
                bF[2 * p + 1][0] = r1; bF[2 * p + 1][1] = r3;
            }
#pragma unroll
            for (int mt = 0; mt < 2; mt++)
#pragma unroll
                for (int nt = 0; nt < 4; nt++)
                    mma_bf16(acc[mt][nt], aF[mt], bF[nt]);
        }
        __syncthreads();
        if (t + 2 < ktiles) {
            load_tile(buf, t + 2);
            CP_COMMIT();
        }
    }

    const int mrow = lane >> 2, ncol = (lane & 3) * 2;
#pragma unroll
    for (int mt = 0; mt < 2; mt++)
#pragma unroll
        for (int nt = 0; nt < 4; nt++) {
            int m = m0 + wm * 32 + mt * 16 + mrow;
            int n = n0 + wn * 32 + nt * 8 + ncol;
            C[(size_t)n * ldC + m]           = acc[mt][nt][0];
            C[(size_t)(n + 1) * ldC + m]     = acc[mt][nt][1];
            C[(size_t)n * ldC + m + 8]       = acc[mt][nt][2];
            C[(size_t)(n + 1) * ldC + m + 8] = acc[mt][nt][3];
        }
}

// ---------------- sparse per-label box-sum accumulation -> g_Tbb[bl][k] ----------------
__global__ __launch_bounds__(512) void acc_kernel(const float* __restrict__ b1) {
    const int bl = blockIdx.x;
    const int b = bl / NL;
    const int l = bl % NL;
    const int oc1 = threadIdx.x;

    __shared__ int msh[NPIX];
    for (int i = threadIdx.x; i < NPIX; i += 512) msh[i] = g_m[b * NPIX + i];
    __syncthreads();

    const int lo[3][3] = {{0, 0, 1}, {0, 0, 1}, {3, 4, 5}};
    const int hi[3][3] = {{18, 19, 20}, {22, 23, 23}, {22, 23, 23}};

    float T9[9];
#pragma unroll
    for (int k = 0; k < 9; k++) T9[k] = 0.f;

    for (int pix = 0; pix < NPIX; pix++) {
        if (msh[pix] != l) continue;
        const float* v = &g_P1[(size_t)(b * NPIX + pix) * M1 + oc1 * 9];
        float vv[9];
#pragma unroll
        for (int t = 0; t < 9; t++) vv[t] = v[t];
        int p = pix / 24, q = pix % 24;

        float rs[3][3];
#pragma unroll
        for (int dr = 0; dr < 3; dr++)
#pragma unroll
            for (int bb = 0; bb < 3; bb++) {
                float s = 0.f;
#pragma unroll
                for (int a = 0; a < 3; a++)
                    if (p >= lo[dr][a] && p <= hi[dr][a]) s += vv[a * 3 + bb];
                rs[dr][bb] = s;
            }
#pragma unroll
        for (int dr = 0; dr < 3; dr++)
#pragma unroll
            for (int dc = 0; dc < 3; dc++) {
                float s = 0.f;
#pragma unroll
                for (int bb = 0; bb < 3; bb++)
                    if (q >= lo[dc][bb] && q <= hi[dc][bb]) s += rs[dr][bb];
                T9[dr * 3 + dc] += s;
            }
    }

    const float nrc[3] = {20.f, 24.f, 20.f};
    float bb1 = b1[oc1];
#pragma unroll
    for (int k = 0; k < 9; k++) {
        float t = (T9[k] + nrc[k / 3] * nrc[k % 3] * bb1) * (1.0f / 576.0f);
        g_Tbb[(size_t)bl * K2 + oc1 * 9 + k] = __float2bfloat16(t);
    }
}

// ---------------- split-K reduce + bias ----------------
__global__ void reduce_k(const float* __restrict__ b2) {
    int i = blockIdx.x * blockDim.x + threadIdx.x;
    if (i >= NPAD * OC2) return;
    const int S = NPAD * OC2;
    float s = 0.f;
#pragma unroll
    for (int z = 0; z < KSPLIT; z++) s += g_part[i + z * S];
    g_out512[i] = s + b2[i & 511];
}

// ---------------- final expansion (float4, streaming stores) ----------------
__global__ void expand_k(const float* __restrict__ w3, const float* __restrict__ b3,
                         float4* __restrict__ out) {
    int i4 = blockIdx.x * blockDim.x + threadIdx.x;
    if (i4 >= TXT_ELEMS / 4) return;
    int c4 = i4 & 127;
    int r = i4 >> 7;
    int l = r % NL;
    int r2 = r / NL;
    int o = r2 % 77;
    int b = r2 / 77;
    float w = __ldg(&w3[o]), bb = __ldg(&b3[o]);
    const float4 v = *(const float4*)&g_out512[((size_t)(b * NL + l) * OC2) + c4 * 4];
    __stcs(&out[i4], make_float4(w * v.x + bb, w * v.y + bb, w * v.z + bb, w * v.w + bb));
}

// ---------------- launch ----------------
extern "C" void kernel_launch(void* const* d_in, const int* in_sizes, int n_in,
                              void* d_out, int out_size) {
    const float* noise   = (const float*)d_in[0];
    const int*   targets = (const int*)  d_in[1];
    const float* w1      = (const float*)d_in[2];
    const float* b1      = (const float*)d_in[3];
    const float* w2      = (const float*)d_in[4];
    const float* b2      = (const float*)d_in[5];
    const float* w3      = (const float*)d_in[6];
    const float* b3      = (const float*)d_in[7];
    float* out      = (float*)d_out;
    float* out_img  = out;
    float* out_text = out + IMG_ELEMS;

    __nv_bfloat16 *pA1, *pBx, *pW2, *pTb;
    float *pP1, *pPart;
    cudaGetSymbolAddress((void**)&pA1,   g_A1b);
    cudaGetSymbolAddress((void**)&pBx,   g_Bxb);
    cudaGetSymbolAddress((void**)&pW2,   g_W2b);
    cudaGetSymbolAddress((void**)&pTb,   g_Tbb);
    cudaGetSymbolAddress((void**)&pP1,   g_P1);
    cudaGetSymbolAddress((void**)&pPart, g_part);

    cudaFuncSetAttribute(gemm_bf16, cudaFuncAttributeMaxDynamicSharedMemorySize, SMEM_SZ);

    // launch order chosen so the 4th launch (ncu -s 5 target) is GEMM1.
    prepA_k<<<XPACK_BLOCKS + 512, 256>>>(noise, w1);                  // 1
    prepB_k<<<W2B_BLOCKS + 912, 256>>>((const float4*)w2, noise, out_img); // 2
    labels_k<<<2, 576>>>(targets);                                    // 3

    // 4: GEMM1: P1[n][m] = sum_ic A1b[m][ic] * Bxb[n][ic]   (1152 x 4608 x 768)
    gemm_bf16<<<dim3(M1 / 128, N1 / 64, 1), 256, SMEM_SZ>>>(pA1, pBx, pP1, K1, K1 / 64, M1, 0);

    // 5: sparse accumulation -> Tbb[bl][k]
    acc_kernel<<<NBL, 512>>>(b1);

    // 6: GEMM2 split-K: part[z][bl][oc2] = sum_{k chunk z} w2b[oc2][k] * Tbb[bl][k]
    gemm_bf16<<<dim3(OC2 / 128, NPAD / 64, KSPLIT), 256, SMEM_SZ>>>(
        pW2, pTb, pPart, K2, K2 / KSPLIT / 64, OC2, NPAD * OC2);
    reduce_k<<<(NPAD * OC2 + 255) / 256, 256>>>(b2);                  // 7

    expand_k<<<(TXT_ELEMS / 4 + 255) / 256, 256>>>(w3, b3, (float4*)out_text); // 8
}

// round 7
// speedup vs baseline: 5.0185x; 1.0549x over previous
#include <cuda_runtime.h>
#include <cuda_bf16.h>
#include <cstdint>

// ---------------- problem constants ----------------
#define B_      2
#define NPIX    576
#define NL      171
#define NBL     342
#define NPAD    384          // padded N for GEMM2 (6 x 64)
#define ICH     768
#define OC1     512
#define OC2     512
#define M1      4608         // OC1*9
#define N1      1152         // B_*NPIX
#define K1      768
#define K2      4608
#define KSPLIT  12
#define IMG_ELEMS  (577*B_*768)
#define TXT_ELEMS  (B_*77*NL*512)

// ---------------- scratch (device globals; zero-initialized at load) ----------------
__device__ __align__(128) __nv_bfloat16 g_A1b[M1 * K1];   // w1 rearranged [m=oc1*9+ab][ic]
__device__ __align__(128) __nv_bfloat16 g_Bxb[N1 * K1];   // x transposed  [n][ic]
__device__ __align__(128) __nv_bfloat16 g_P1b[(size_t)N1 * M1];  // GEMM1 out, bf16
__device__ __align__(128) __nv_bfloat16 g_W2b[OC2 * K2];  // w2 cast (already K-major)
__device__ __align__(128) __nv_bfloat16 g_Tbb[NPAD * K2]; // [bl][k]; rows >=342 stay zero
__device__ __align__(128) float         g_part[KSPLIT * NPAD * OC2];
__device__ __align__(128) float         g_out512[NPAD * OC2];
__device__ int g_m[N1];

// ---------------- PTX helpers (sm_80 base-target features only) ----------------
__device__ __forceinline__ uint32_t smem_u32(const void* p) {
    uint32_t a;
    asm("{ .reg .u64 t; cvta.to.shared.u64 t, %1; cvt.u32.u64 %0, t; }" : "=r"(a) : "l"(p));
    return a;
}
__device__ __forceinline__ void cpasync16(uint32_t dst, const void* src) {
    asm volatile("cp.async.cg.shared.global [%0], [%1], 16;\n" :: "r"(dst), "l"(src));
}
#define CP_COMMIT() asm volatile("cp.async.commit_group;\n" ::: "memory")

__device__ __forceinline__ void ldsm_x4(uint32_t& r0, uint32_t& r1, uint32_t& r2,
                                        uint32_t& r3, uint32_t addr) {
    asm volatile("ldmatrix.sync.aligned.m8n8.x4.shared.b16 {%0,%1,%2,%3}, [%4];"
                 : "=r"(r0), "=r"(r1), "=r"(r2), "=r"(r3) : "r"(addr));
}
__device__ __forceinline__ void mma_bf16(float* c, const uint32_t* a, const uint32_t* b) {
    asm volatile("mma.sync.aligned.m16n8k16.row.col.f32.bf16.bf16.f32 "
                 "{%0,%1,%2,%3}, {%4,%5,%6,%7}, {%8,%9}, {%0,%1,%2,%3};"
                 : "+f"(c[0]), "+f"(c[1]), "+f"(c[2]), "+f"(c[3])
                 : "r"(a[0]), "r"(a[1]), "r"(a[2]), "r"(a[3]), "r"(b[0]), "r"(b[1]));
}

// output-type helpers
__device__ __forceinline__ void store_c(float* p, float v) { *p = v; }
__device__ __forceinline__ void store_c(__nv_bfloat16* p, float v) { *p = __float2bfloat16(v); }

// ---------------- labels ----------------
__global__ void labels_k(const int* __restrict__ targets) {
    int i = blockIdx.x * blockDim.x + threadIdx.x;
    if (i >= N1) return;
    int b = i / NPIX, pix = i % NPIX;
    int pi = pix / 24, qj = pix % 24;
    g_m[i] = targets[b * 147456 + (pi * 16) * 384 + qj * 16];
}

// ---------------- fused prep A: xpack (864 blocks) + w1r (512 blocks) ----------------
#define XPACK_BLOCKS (18 * 24 * 2)   // 864
__global__ __launch_bounds__(256) void prepA_k(const float* __restrict__ noise,
                                               const float* __restrict__ w1) {
    int bid = blockIdx.x;
    if (bid < XPACK_BLOCKS) {
        __shared__ float tile[32][33];
        int b = bid / (18 * 24);
        int r0 = bid % (18 * 24);
        int p0 = (r0 % 18) * 32, c0 = (r0 / 18) * 32;
        int tx = threadIdx.x & 31, ty = threadIdx.x >> 5;
        for (int r = ty; r < 32; r += 8)
            tile[r][tx] = noise[(size_t)b * 443136 + (c0 + r) * 577 + 1 + p0 + tx];
        __syncthreads();
        for (int r = ty; r < 32; r += 8)
            g_Bxb[(size_t)(b * NPIX + p0 + r) * ICH + c0 + tx] = __float2bfloat16(tile[tx][r]);
    } else {
        __shared__ float sm[ICH * 9];
        int oc1 = bid - XPACK_BLOCKS;
        const float4* src = (const float4*)(w1 + (size_t)oc1 * ICH * 9);
        for (int i = threadIdx.x; i < ICH * 9 / 4; i += 256)
            ((float4*)sm)[i] = src[i];
        __syncthreads();
        uint32_t* dst = (uint32_t*)(g_A1b + (size_t)oc1 * 9 * K1);
        for (int j2 = threadIdx.x; j2 < ICH * 9 / 2; j2 += 256) {
            int j = j2 * 2;
            int ab = j / ICH, ic = j - ab * ICH;
            __nv_bfloat162 v;
            v.x = __float2bfloat16(sm[ic * 9 + ab]);
            v.y = __float2bfloat16(sm[(ic + 1) * 9 + ab]);
            dst[j2] = *(uint32_t*)&v;
        }
    }
}

// ---------------- fused prep B: w2 cast (2304 blocks) + img transpose (912 blocks) ----------------
#define W2B_BLOCKS 2304
__global__ __launch_bounds__(256) void prepB_k(const float4* __restrict__ w2,
                                               const float* __restrict__ noise,
                                               float* __restrict__ out_img) {
    int bid = blockIdx.x;
    if (bid < W2B_BLOCKS) {
        int i = bid * 256 + threadIdx.x;
        float4 v = w2[i];
        __nv_bfloat162 lo, hi;
        lo.x = __float2bfloat16(v.x); lo.y = __float2bfloat16(v.y);
        hi.x = __float2bfloat16(v.z); hi.y = __float2bfloat16(v.w);
        uint2 o;
        o.x = *(uint32_t*)&lo; o.y = *(uint32_t*)&hi;
        ((uint2*)g_W2b)[i] = o;
    } else {
        __shared__ float tile[32][33];
        int t = bid - W2B_BLOCKS;            // 0..911 = 19*24*2
        int b = t / (19 * 24);
        int r0 = t % (19 * 24);
        int s0 = (r0 % 19) * 32, c0 = (r0 / 19) * 32;
        int tx = threadIdx.x & 31, ty = threadIdx.x >> 5;
        for (int r = ty; r < 32; r += 8) {
            int s = s0 + tx;
            if (s < 577) tile[r][tx] = noise[(size_t)b * 443136 + (c0 + r) * 577 + s];
        }
        __syncthreads();
        for (int r = ty; r < 32; r += 8) {
            int s = s0 + r;
            if (s < 577) out_img[(size_t)s * (B_ * 768) + b * 768 + c0 + tx] = tile[tx][r];
        }
    }
}

// ---------------- bf16 mma.sync GEMM:  C[n][m] = sum_k A[m][k]*B[n][k] ----------------
// 128(M)x64(N) block tile, BK=64, 256 threads (8 warps: 4 m x 2 n), warp tile 32x32.
// Double-buffered cp.async stages + double-buffered register fragments:
// ldsm for ks+1 issues while mma of ks executes (breaks ldsm->mma serialization).
#define RSTRIDE 144   // smem row pitch bytes (64 bf16 + 16B pad) -> conflict-free ldmatrix
#define A_ROWS  128
#define B_ROWS  64
#define BUFSZ   ((A_ROWS + B_ROWS) * RSTRIDE)   // 27648 per stage
#define SMEM_SZ (2 * BUFSZ)                     // 55296

template <typename OutT>
__global__ __launch_bounds__(256) void gemm_bf16(
    const __nv_bfloat16* __restrict__ A, const __nv_bfloat16* __restrict__ B,
    OutT* __restrict__ C, int ldk, int ktiles, int ldC, int zstride)
{
    extern __shared__ __align__(128) char smem_raw[];
    const uint32_t sbase = smem_u32(smem_raw);
    const int tid = threadIdx.x;
    const int lane = tid & 31, wid = tid >> 5;
    const int wm = wid & 3, wn = wid >> 2;
    const int m0 = blockIdx.x * 128, n0 = blockIdx.y * 64;
    const int kofs = blockIdx.z * ktiles * 64;
    C += (size_t)blockIdx.z * zstride;

    float acc[2][4][4];
#pragma unroll
    for (int i = 0; i < 2; i++)
#pragma unroll
        for (int j = 0; j < 4; j++)
#pragma unroll
            for (int q = 0; q < 4; q++) acc[i][j][q] = 0.f;

    auto load_tile = [&](int buf, int t) {
        uint32_t s = sbase + buf * BUFSZ;
        int k = kofs + t * 64;
#pragma unroll
        for (int i = 0; i < 6; i++) {
            int ch = tid + i * 256;        // 0..1535 (A: 0..1023, B: 1024..1535)
            int isB = ch >> 10;
            int row = (ch >> 3) & (isB ? 63 : 127);
            int c8 = ch & 7;
            uint32_t dst = s + isB * (A_ROWS * RSTRIDE) + row * RSTRIDE + c8 * 16;
            const __nv_bfloat16* src =
                (isB ? B + (size_t)(n0 + row) * ldk : A + (size_t)(m0 + row) * ldk)
                + k + c8 * 8;
            cpasync16(dst, src);
        }
    };

    load_tile(0, 0);
    CP_COMMIT();
    if (ktiles > 1) { load_tile(1, 1); }
    CP_COMMIT();

    const uint32_t rsel = lane & 15;
    const uint32_t chi = (lane >> 4) * 16;

    // register fragments, double buffered across ks steps
    uint32_t aF[2][2][4];   // [fbuf][mt][4]
    uint32_t bF[2][4][2];   // [fbuf][nt][2]

    auto ld_frags = [&](int fb, uint32_t sA, uint32_t sB, int ks) {
        uint32_t colB = ks * 32 + chi;
#pragma unroll
        for (int mt = 0; mt < 2; mt++) {
            uint32_t addr = sA + (wm * 32 + mt * 16 + rsel) * RSTRIDE + colB;
            ldsm_x4(aF[fb][mt][0], aF[fb][mt][1], aF[fb][mt][2], aF[fb][mt][3], addr);
        }
#pragma unroll
        for (int p = 0; p < 2; p++) {
            uint32_t r0, r1, r2, r3;
            uint32_t addr = sB + (wn * 32 + p * 16 + rsel) * RSTRIDE + colB;
            ldsm_x4(r0, r1, r2, r3, addr);
            bF[fb][2 * p][0] = r0; bF[fb][2 * p][1] = r2;
            bF[fb][2 * p + 1][0] = r1; bF[fb][2 * p + 1][1] = r3;
        }
    };
    auto do_mma = [&](int fb) {
#pragma unroll
        for (int mt = 0; mt < 2; mt++)
#pragma unroll
            for (int nt = 0; nt < 4; nt++)
                mma_bf16(acc[mt][nt], aF[fb][mt], bF[fb][nt]);
    };

    for (int t = 0; t < ktiles; t++) {
        if (t + 1 < ktiles)
            asm volatile("cp.async.wait_group 1;\n" ::: "memory");
        else
            asm volatile("cp.async.wait_group 0;\n" ::: "memory");
        __syncthreads();

        int buf = t & 1;
        uint32_t sA = sbase + buf * BUFSZ;
        uint32_t sB = sA + A_ROWS * RSTRIDE;

        ld_frags(0, sA, sB, 0);
        ld_frags(1, sA, sB, 1);      // prefetch ks=1
        do_mma(0);                   // ks=0
        ld_frags(0, sA, sB, 2);      // prefetch ks=2
        do_mma(1);                   // ks=1
        ld_frags(1, sA, sB, 3);      // prefetch ks=3 (last smem read of this tile)
        do_mma(0);                   // ks=2
        __syncthreads();             // all warps done reading this buf
        if (t + 2 < ktiles) {
            load_tile(buf, t + 2);   // overwrite while ks=3 mma runs
            CP_COMMIT();
        }
        do_mma(1);                   // ks=3
    }

    const int mrow = lane >> 2, ncol = (lane & 3) * 2;
#pragma unroll
    for (int mt = 0; mt < 2; mt++)
#pragma unroll
        for (int nt = 0; nt < 4; nt++) {
            int m = m0 + wm * 32 + mt * 16 + mrow;
            int n = n0 + wn * 32 + nt * 8 + ncol;
            store_c(&C[(size_t)n * ldC + m],           acc[mt][nt][0]);
            store_c(&C[(size_t)(n + 1) * ldC + m],     acc[mt][nt][1]);
            store_c(&C[(size_t)n * ldC + m + 8],       acc[mt][nt][2]);
            store_c(&C[(size_t)(n + 1) * ldC + m + 8], acc[mt][nt][3]);
        }
}

// ---------------- sparse per-label box-sum accumulation -> g_Tbb[bl][k] ----------------
__global__ __launch_bounds__(512) void acc_kernel(const float* __restrict__ b1) {
    const int bl = blockIdx.x;
    const int b = bl / NL;
    const int l = bl % NL;
    const int oc1 = threadIdx.x;

    __shared__ int msh[NPIX];
    for (int i = threadIdx.x; i < NPIX; i += 512) msh[i] = g_m[b * NPIX + i];
    __syncthreads();

    const int lo[3][3] = {{0, 0, 1}, {0, 0, 1}, {3, 4, 5}};
    const int hi[3][3] = {{18, 19, 20}, {22, 23, 23}, {22, 23, 23}};

    float T9[9];
#pragma unroll
    for (int k = 0; k < 9; k++) T9[k] = 0.f;

    for (int pix = 0; pix < NPIX; pix++) {
        if (msh[pix] != l) continue;
        const __nv_bfloat16* v = &g_P1b[(size_t)(b * NPIX + pix) * M1 + oc1 * 9];
        float vv[9];
#pragma unroll
        for (int t = 0; t < 9; t++) vv[t] = __bfloat162float(v[t]);
        int p = pix / 24, q = pix % 24;

        float rs[3][3];
#pragma unroll
        for (int dr = 0; dr < 3; dr++)
#pragma unroll
            for (int bb = 0; bb < 3; bb++) {
                float s = 0.f;
#pragma unroll
                for (int a = 0; a < 3; a++)
                    if (p >= lo[dr][a] && p <= hi[dr][a]) s += vv[a * 3 + bb];
                rs[dr][bb] = s;
            }
#pragma unroll
        for (int dr = 0; dr < 3; dr++)
#pragma unroll
            for (int dc = 0; dc < 3; dc++) {
                float s = 0.f;
#pragma unroll
                for (int bb = 0; bb < 3; bb++)
                    if (q >= lo[dc][bb] && q <= hi[dc][bb]) s += rs[dr][bb];
                T9[dr * 3 + dc] += s;
            }
    }

    const float nrc[3] = {20.f, 24.f, 20.f};
    float bb1 = b1[oc1];
#pragma unroll
    for (int k = 0; k < 9; k++) {
        float t = (T9[k] + nrc[k / 3] * nrc[k % 3] * bb1) * (1.0f / 576.0f);
        g_Tbb[(size_t)bl * K2 + oc1 * 9 + k] = __float2bfloat16(t);
    }
}

// ---------------- split-K reduce + bias ----------------
__global__ void reduce_k(const float* __restrict__ b2) {
    int i = blockIdx.x * blockDim.x + threadIdx.x;
    if (i >= NPAD * OC2) return;
    const int S = NPAD * OC2;
    float s = 0.f;
#pragma unroll
    for (int z = 0; z < KSPLIT; z++) s += g_part[i + z * S];
    g_out512[i] = s + b2[i & 511];
}

// ---------------- final expansion (float4, streaming stores) ----------------
__global__ void expand_k(const float* __restrict__ w3, const float* __restrict__ b3,
                         float4* __restrict__ out) {
    int i4 = blockIdx.x * blockDim.x + threadIdx.x;
    if (i4 >= TXT_ELEMS / 4) return;
    int c4 = i4 & 127;
    int r = i4 >> 7;
    int l = r % NL;
    int r2 = r / NL;
    int o = r2 % 77;
    int b = r2 / 77;
    float w = __ldg(&w3[o]), bb = __ldg(&b3[o]);
    const float4 v = *(const float4*)&g_out512[((size_t)(b * NL + l) * OC2) + c4 * 4];
    __stcs(&out[i4], make_float4(w * v.x + bb, w * v.y + bb, w * v.z + bb, w * v.w + bb));
}

// ---------------- launch ----------------
extern "C" void kernel_launch(void* const* d_in, const int* in_sizes, int n_in,
                              void* d_out, int out_size) {
    const float* noise   = (const float*)d_in[0];
    const int*   targets = (const int*)  d_in[1];
    const float* w1      = (const float*)d_in[2];
    const float* b1      = (const float*)d_in[3];
    const float* w2      = (const float*)d_in[4];
    const float* b2      = (const float*)d_in[5];
    const float* w3      = (const float*)d_in[6];
    const float* b3      = (const float*)d_in[7];
    float* out      = (float*)d_out;
    float* out_img  = out;
    float* out_text = out + IMG_ELEMS;

    __nv_bfloat16 *pA1, *pBx, *pW2, *pTb, *pP1;
    float *pPart;
    cudaGetSymbolAddress((void**)&pA1,   g_A1b);
    cudaGetSymbolAddress((void**)&pBx,   g_Bxb);
    cudaGetSymbolAddress((void**)&pW2,   g_W2b);
    cudaGetSymbolAddress((void**)&pTb,   g_Tbb);
    cudaGetSymbolAddress((void**)&pP1,   g_P1b);
    cudaGetSymbolAddress((void**)&pPart, g_part);

    cudaFuncSetAttribute(gemm_bf16<__nv_bfloat16>,
                         cudaFuncAttributeMaxDynamicSharedMemorySize, SMEM_SZ);
    cudaFuncSetAttribute(gemm_bf16<float>,
                         cudaFuncAttributeMaxDynamicSharedMemorySize, SMEM_SZ);

    // launch order chosen so the 4th launch (ncu -s 5 target) is GEMM1.
    prepA_k<<<XPACK_BLOCKS + 512, 256>>>(noise, w1);                  // 1
    prepB_k<<<W2B_BLOCKS + 912, 256>>>((const float4*)w2, noise, out_img); // 2
    labels_k<<<2, 576>>>(targets);                                    // 3

    // 4: GEMM1: P1[n][m] = sum_ic A1b[m][ic] * Bxb[n][ic]   (1152 x 4608 x 768)
    gemm_bf16<__nv_bfloat16><<<dim3(M1 / 128, N1 / 64, 1), 256, SMEM_SZ>>>(
        pA1, pBx, pP1, K1, K1 / 64, M1, 0);

    // 5: sparse accumulation -> Tbb[bl][k]
    acc_kernel<<<NBL, 512>>>(b1);

    // 6: GEMM2 split-K: part[z][bl][oc2] = sum_{k chunk z} w2b[oc2][k] * Tbb[bl][k]
    gemm_bf16<float><<<dim3(OC2 / 128, NPAD / 64, KSPLIT), 256, SMEM_SZ>>>(
        pW2, pTb, pPart, K2, K2 / KSPLIT / 64, OC2, NPAD * OC2);
    reduce_k<<<(NPAD * OC2 + 255) / 256, 256>>>(b2);                  // 7

    expand_k<<<(TXT_ELEMS / 4 + 255) / 256, 256>>>(w3, b3, (float4*)out_text); // 8
}